// round 14
// baseline (speedup 1.0000x reference)
#include <cuda_runtime.h>
#include <cuda_bf16.h>
#include <cuda_fp16.h>
#include <cstdint>

static constexpr int F1 = 128;
static constexpr int F2 = 64;
static constexpr int NMAX = 100000;
static constexpr int NPAD = 100096;       // 782 * 128
static constexpr int EMAX = 1600000;
static constexpr int TOT  = 3 * NMAX;

// ---------------------------------------------------------------------------
// device scratch (zero-initialized at module load; padded rows stay 0 forever)
// ---------------------------------------------------------------------------
__device__ int   g_hist   [TOT];
__device__ int   g_chunk  [TOT];
__device__ int   g_off    [TOT];
__device__ int   g_cursor [TOT];
__device__ int   g_partial[2048];
__device__ float g_dinv   [TOT];
__device__ int2  g_csr    [3 * EMAX];
__device__ __half g_xh  [(size_t)NPAD * F1];       // fp16 x
__device__ __half g_y   [(size_t)3 * NPAD * F1];   // fp16 y
__device__ __half g_z   [(size_t)3 * NPAD * F2];   // fp16 z
__device__ __half g_w1t0[3 * 128 * 128];           // fp16 W1^T hi
__device__ __half g_w1t1[3 * 128 * 128];           // fp16 W1^T lo
__device__ __half g_w2t0[3 * 64 * 128];            // fp16 W2^T hi, stacked [192][128]
__device__ __half g_w2t1[3 * 64 * 128];

// ---------------------------------------------------------------------------
// mma.sync f16
// ---------------------------------------------------------------------------
__device__ __forceinline__ void mma_f16(float* c, const uint32_t* a, uint32_t b0, uint32_t b1) {
    asm volatile("mma.sync.aligned.m16n8k16.row.col.f32.f16.f16.f32 "
        "{%0,%1,%2,%3}, {%4,%5,%6,%7}, {%8,%9}, {%0,%1,%2,%3};"
        : "+f"(c[0]), "+f"(c[1]), "+f"(c[2]), "+f"(c[3])
        : "r"(a[0]), "r"(a[1]), "r"(a[2]), "r"(a[3]), "r"(b0), "r"(b1));
}

// ---------------------------------------------------------------------------
// fused prep: x->fp16 ; W1/W2 fp16 splits ; zero hist
// ---------------------------------------------------------------------------
__device__ __forceinline__ void wsplit_one(const float* __restrict__ W, __half* __restrict__ o0,
                                           __half* __restrict__ o1, int j, int K, int N) {
    int k = j % K;
    int nn = (j / K) % N;
    int t = j / (K * N);
    float w = __ldg(&W[((size_t)t * K + k) * N + nn]);
    __half h0 = __float2half_rn(w);
    float r = w - __half2float(h0);
    size_t o = ((size_t)t * N + nn) * K + k;
    o0[o] = h0;
    o1[o] = __float2half_rn(r);
}

__global__ void k_prep(const float* __restrict__ x, __half* __restrict__ xh,
                       const float* __restrict__ W1, __half* __restrict__ w1t0,
                       __half* __restrict__ w1t1,
                       const float* __restrict__ W2, __half* __restrict__ w2t0,
                       __half* __restrict__ w2t1, int* __restrict__ hist, int n) {
    int i = blockIdx.x * blockDim.x + threadIdx.x;
    int nx = n * 32;
    const int w1n = 3 * 128 * 128, w2n = 3 * 128 * 64;
    if (i < nx) {
        float4 v = __ldg((const float4*)x + i);
        __half2* o = (__half2*)xh + (size_t)i * 2;
        o[0] = __floats2half2_rn(v.x, v.y);
        o[1] = __floats2half2_rn(v.z, v.w);
    } else if (i < nx + w1n) {
        wsplit_one(W1, w1t0, w1t1, i - nx, 128, 128);
    } else if (i < nx + w1n + w2n) {
        wsplit_one(W2, w2t0, w2t1, i - nx - w1n, 128, 64);
    } else if (i < nx + w1n + w2n + 3 * n) {
        hist[i - nx - w1n - w2n] = 0;
    }
}

// ---------------------------------------------------------------------------
// CSR build
// ---------------------------------------------------------------------------
// 8 edges per thread (2x int4)
__global__ void k_hist8(const int* __restrict__ edges, int* __restrict__ hist, int E, int n) {
    int i = blockIdx.x * blockDim.x + threadIdx.x;
    int eo = E >> 3;
    if (i >= 3 * eo) return;
    int t = i / eo, g = i - t * eo;
    const int4* dp = (const int4*)(edges + (size_t)t * 2 * E + E) + g * 2;
    int4 d0 = __ldg(dp);
    int4 d1 = __ldg(dp + 1);
    int* h = hist + t * n;
    atomicAdd(&h[d0.x], 1);
    atomicAdd(&h[d0.y], 1);
    atomicAdd(&h[d0.z], 1);
    atomicAdd(&h[d0.w], 1);
    atomicAdd(&h[d1.x], 1);
    atomicAdd(&h[d1.y], 1);
    atomicAdd(&h[d1.z], 1);
    atomicAdd(&h[d1.w], 1);
}

template<int NW>
__device__ __forceinline__ int block_excl_scan(int v, int tid, int* total) {
    __shared__ int wsum[NW];
    int lane = tid & 31, w = tid >> 5;
    int inc = v;
#pragma unroll
    for (int o = 1; o < 32; o <<= 1) {
        int t = __shfl_up_sync(0xffffffffu, inc, o);
        if (lane >= o) inc += t;
    }
    if (lane == 31) wsum[w] = inc;
    __syncthreads();
    if (w == 0) {
        int s = (lane < NW) ? wsum[lane] : 0;
#pragma unroll
        for (int o = 1; o < NW; o <<= 1) {
            int t = __shfl_up_sync(0xffffffffu, s, o);
            if (lane >= o) s += t;
        }
        if (lane < NW) wsum[lane] = s;
    }
    __syncthreads();
    int wbase = (w == 0) ? 0 : wsum[w - 1];
    *total = wsum[NW - 1];
    __syncthreads();
    return wbase + inc - v;
}

// scan1: 4 elements per thread (1024 per block)
__global__ void k_scan1v(const int* __restrict__ in, int* __restrict__ chunk,
                         int* __restrict__ partial, int total) {
    int tid = threadIdx.x;
    int base = blockIdx.x * 1024 + tid * 4;
    int v0 = 0, v1 = 0, v2 = 0, v3 = 0;
    if (base + 3 < total) {
        int4 v = *(const int4*)(in + base);
        v0 = v.x; v1 = v.y; v2 = v.z; v3 = v.w;
    } else if (base < total) {
        v0 = in[base];
        if (base + 1 < total) v1 = in[base + 1];
        if (base + 2 < total) v2 = in[base + 2];
    }
    int tsum;
    int ex = block_excl_scan<8>(v0 + v1 + v2 + v3, tid, &tsum);
    if (base + 3 < total) {
        int4 o = make_int4(ex, ex + v0, ex + v0 + v1, ex + v0 + v1 + v2);
        *(int4*)(chunk + base) = o;
    } else if (base < total) {
        chunk[base] = ex;
        if (base + 1 < total) chunk[base + 1] = ex + v0;
        if (base + 2 < total) chunk[base + 2] = ex + v0 + v1;
    }
    if (tid == 0) partial[blockIdx.x] = tsum;
}
__global__ void k_scan2(int* __restrict__ partial, int nblocks) {
    __shared__ int running;
    int tid = threadIdx.x;
    if (tid == 0) running = 0;
    __syncthreads();
    for (int base = 0; base < nblocks; base += 1024) {
        int i = base + tid;
        int v = (i < nblocks) ? partial[i] : 0;
        int tsum;
        int ex = block_excl_scan<32>(v, tid, &tsum);
        if (i < nblocks) partial[i] = ex + running;
        __syncthreads();
        if (tid == 0) running += tsum;
        __syncthreads();
    }
}
// scan3: 4 elements per thread; fused off/cursor/dinv
__global__ void k_scan3fv(const int* __restrict__ chunk, const int* __restrict__ partial,
                          const int* __restrict__ hist, int* __restrict__ off,
                          int* __restrict__ cursor, float* __restrict__ dinv, int total) {
    int base = blockIdx.x * 1024 + threadIdx.x * 4;
    int pb = partial[blockIdx.x];
    if (base + 3 < total) {
        int4 c = *(const int4*)(chunk + base);
        int4 h = *(const int4*)(hist + base);
        int4 o = make_int4(c.x + pb, c.y + pb, c.z + pb, c.w + pb);
        *(int4*)(off + base) = o;
        *(int4*)(cursor + base) = o;
        float4 d = make_float4(rsqrtf((float)h.x + 1.0f), rsqrtf((float)h.y + 1.0f),
                               rsqrtf((float)h.z + 1.0f), rsqrtf((float)h.w + 1.0f));
        *(float4*)(dinv + base) = d;
    } else {
        for (int j = 0; j < 4; j++) {
            int i = base + j;
            if (i < total) {
                int v = chunk[i] + pb;
                off[i] = v;
                cursor[i] = v;
                dinv[i] = rsqrtf((float)hist[i] + 1.0f);
            }
        }
    }
}
__global__ void k_permute4(const int* __restrict__ edges, const float* __restrict__ dinv,
                           int* __restrict__ cursor, int2* __restrict__ csr, int E, int n) {
    int i = blockIdx.x * blockDim.x + threadIdx.x;
    int eq = E >> 2;
    if (i >= 3 * eq) return;
    int t = i / eq, g = i - t * eq;
    const int* base = edges + (size_t)t * 2 * E;
    int4 s4 = __ldg((const int4*)base + g);
    int4 d4 = __ldg((const int4*)(base + E) + g);
    const float* dv = dinv + t * n;
    int* cur = cursor + t * n;
#pragma unroll
    for (int j = 0; j < 4; j++) {
        int s = (j == 0) ? s4.x : (j == 1) ? s4.y : (j == 2) ? s4.z : s4.w;
        int d = (j == 0) ? d4.x : (j == 1) ? d4.y : (j == 2) ? d4.z : d4.w;
        int pos = atomicAdd(&cur[d], 1);
        float c = __ldg(&dv[s]) * __ldg(&dv[d]);
        csr[pos] = make_int2(s, __float_as_int(c));
    }
}

// ---------------------------------------------------------------------------
// layer-1 aggregation (round-10/12 winner form): one warp per (relation,node)
// ---------------------------------------------------------------------------
__device__ __forceinline__ void fma_h4(float4& acc, uint2 xv, float c) {
    float2 f0 = __half22float2(*reinterpret_cast<__half2*>(&xv.x));
    float2 f1 = __half22float2(*reinterpret_cast<__half2*>(&xv.y));
    acc.x += f0.x * c; acc.y += f0.y * c; acc.z += f1.x * c; acc.w += f1.y * c;
}

__global__ void __launch_bounds__(256)
k_agg1(const __half* __restrict__ xh, const float* __restrict__ dinv,
       const int* __restrict__ off, const int2* __restrict__ csr,
       __half* __restrict__ y, int n) {
    int wid = threadIdx.x >> 5, lane = threadIdx.x & 31;
    int node = blockIdx.x * 8 + wid;
    if (node >= n) return;
    int t = blockIdx.y;
    int idx = t * n + node;
    int row_s = __ldg(&off[idx]);
    int row_e = (idx == 3 * n - 1) ? 3 * EMAX : __ldg(&off[idx + 1]);
    float di = __ldg(&dinv[idx]);
    const uint2* xv = (const uint2*)xh;
    float4 acc = make_float4(0.f, 0.f, 0.f, 0.f);
    fma_h4(acc, __ldg(xv + (size_t)node * 32 + lane), di * di);
    int e = row_s;
    for (; e + 4 <= row_e; e += 4) {
        int2 p0 = __ldg(&csr[e]);
        int2 p1 = __ldg(&csr[e + 1]);
        int2 p2 = __ldg(&csr[e + 2]);
        int2 p3 = __ldg(&csr[e + 3]);
        uint2 v0 = __ldg(xv + (size_t)p0.x * 32 + lane);
        uint2 v1 = __ldg(xv + (size_t)p1.x * 32 + lane);
        uint2 v2 = __ldg(xv + (size_t)p2.x * 32 + lane);
        uint2 v3 = __ldg(xv + (size_t)p3.x * 32 + lane);
        fma_h4(acc, v0, __int_as_float(p0.y));
        fma_h4(acc, v1, __int_as_float(p1.y));
        fma_h4(acc, v2, __int_as_float(p2.y));
        fma_h4(acc, v3, __int_as_float(p3.y));
    }
    for (; e < row_e; e++) {
        int2 p = __ldg(&csr[e]);
        fma_h4(acc, __ldg(xv + (size_t)p.x * 32 + lane), __int_as_float(p.y));
    }
    size_t base = ((size_t)t * NPAD + node) * 64 + lane * 2;
    ((__half2*)y)[base]     = __floats2half2_rn(acc.x, acc.y);
    ((__half2*)y)[base + 1] = __floats2half2_rn(acc.z, acc.w);
}

// ---------------------------------------------------------------------------
// FUSED GEMM v2 (round-12 winner) with minBlocks=2 register cap: 104960 B smem
// ---------------------------------------------------------------------------
static constexpr int LDS_PAD = 136;
static constexpr int GF_SMEM = 104448 + 512;
__global__ void __launch_bounds__(256, 2)
k_gemm_fused(const __half* __restrict__ y, const __half* __restrict__ w10,
             const __half* __restrict__ w11, const float* __restrict__ b1,
             const __half* __restrict__ w20, const __half* __restrict__ w21,
             __half* __restrict__ z) {
    extern __shared__ char smem[];
    __half* A_s = (__half*)smem;
    float* sumb = (float*)(smem + 104448);

    const int tid = threadIdx.x, wid = tid >> 5, lane = tid & 31;
    const int gid = lane >> 2, tid4 = lane & 3;
    const int row0 = blockIdx.x * 128;
    const int m0 = (wid & 3) * 32;

    if (tid < 128) sumb[tid] = __ldg(&b1[tid]) + __ldg(&b1[128 + tid]) + __ldg(&b1[256 + tid]);

    // ---------------- phase 1: h tile into A_s ----------------
    {
        __half* B_s[2] = { (__half*)(smem + 34816), (__half*)(smem + 69632) };
        const int n0 = (wid >> 2) * 64;

        float acc[2][8][4];
#pragma unroll
        for (int mi = 0; mi < 2; mi++)
#pragma unroll
            for (int ni = 0; ni < 8; ni++)
#pragma unroll
                for (int c = 0; c < 4; c++) acc[mi][ni][c] = 0.0f;

        for (int t = 0; t < 3; t++) {
            const __half* Ag  = y   + ((size_t)t * NPAD + row0) * 128;
            const __half* Bg0 = w10 + (size_t)t * 16384;
            const __half* Bg1 = w11 + (size_t)t * 16384;
            __syncthreads();
#pragma unroll
            for (int i = tid; i < 2048; i += 256) {
                int r = i >> 4, c = i & 15;
                *(uint4*)&A_s[r * LDS_PAD + c * 8]    = *(const uint4*)(Ag  + (size_t)r * 128 + c * 8);
                *(uint4*)&B_s[0][r * LDS_PAD + c * 8] = *(const uint4*)(Bg0 + (size_t)r * 128 + c * 8);
                *(uint4*)&B_s[1][r * LDS_PAD + c * 8] = *(const uint4*)(Bg1 + (size_t)r * 128 + c * 8);
            }
            __syncthreads();
#pragma unroll
            for (int ks = 0; ks < 8; ks++) {
                int k0 = ks * 16;
                uint32_t a[2][4];
#pragma unroll
                for (int mi = 0; mi < 2; mi++) {
                    int r = m0 + mi * 16 + gid;
                    a[mi][0] = *(const uint32_t*)&A_s[r * LDS_PAD + k0 + tid4 * 2];
                    a[mi][1] = *(const uint32_t*)&A_s[(r + 8) * LDS_PAD + k0 + tid4 * 2];
                    a[mi][2] = *(const uint32_t*)&A_s[r * LDS_PAD + k0 + 8 + tid4 * 2];
                    a[mi][3] = *(const uint32_t*)&A_s[(r + 8) * LDS_PAD + k0 + 8 + tid4 * 2];
                }
#pragma unroll
                for (int bp = 0; bp < 2; bp++) {
                    const __half* Bp = B_s[bp];
#pragma unroll
                    for (int ni = 0; ni < 8; ni++) {
                        int nr = n0 + ni * 8 + gid;
                        uint32_t b0 = *(const uint32_t*)&Bp[nr * LDS_PAD + k0 + tid4 * 2];
                        uint32_t b1v = *(const uint32_t*)&Bp[nr * LDS_PAD + k0 + 8 + tid4 * 2];
                        mma_f16(acc[0][ni], a[0], b0, b1v);
                        mma_f16(acc[1][ni], a[1], b0, b1v);
                    }
                }
            }
        }
        __syncthreads();   // all A_s/B_s reads of phase 1 done; write h tile
#pragma unroll
        for (int mi = 0; mi < 2; mi++) {
#pragma unroll
            for (int half = 0; half < 2; half++) {
                int row = m0 + mi * 16 + gid + half * 8;
#pragma unroll
                for (int ni = 0; ni < 8; ni++) {
                    int col = n0 + ni * 8 + tid4 * 2;
                    float f0 = fmaxf((acc[mi][ni][half * 2]     + sumb[col])     * (1.0f / 3.0f), 0.0f);
                    float f1 = fmaxf((acc[mi][ni][half * 2 + 1] + sumb[col + 1]) * (1.0f / 3.0f), 0.0f);
                    *(__half2*)&A_s[row * LDS_PAD + col] = __floats2half2_rn(f0, f1);
                }
            }
        }
    }

    // ---------------- phase 2: z = h @ W2^T in two N-halves ----------------
    {
        __half* B_s[2] = { (__half*)(smem + 34816), (__half*)(smem + 60928) };
        const int n0 = (wid >> 2) * 48;

        for (int nh = 0; nh < 2; nh++) {
            const __half* Bg0 = w20 + (size_t)nh * 96 * 128;
            const __half* Bg1 = w21 + (size_t)nh * 96 * 128;
            __syncthreads();
#pragma unroll
            for (int i = tid; i < 1536; i += 256) {
                int r = i >> 4, c = i & 15;
                *(uint4*)&B_s[0][r * LDS_PAD + c * 8] = *(const uint4*)(Bg0 + (size_t)r * 128 + c * 8);
                *(uint4*)&B_s[1][r * LDS_PAD + c * 8] = *(const uint4*)(Bg1 + (size_t)r * 128 + c * 8);
            }
            __syncthreads();

            float acc[2][6][4];
#pragma unroll
            for (int mi = 0; mi < 2; mi++)
#pragma unroll
                for (int ni = 0; ni < 6; ni++)
#pragma unroll
                    for (int c = 0; c < 4; c++) acc[mi][ni][c] = 0.0f;

#pragma unroll
            for (int ks = 0; ks < 8; ks++) {
                int k0 = ks * 16;
                uint32_t a[2][4];
#pragma unroll
                for (int mi = 0; mi < 2; mi++) {
                    int r = m0 + mi * 16 + gid;
                    a[mi][0] = *(const uint32_t*)&A_s[r * LDS_PAD + k0 + tid4 * 2];
                    a[mi][1] = *(const uint32_t*)&A_s[(r + 8) * LDS_PAD + k0 + tid4 * 2];
                    a[mi][2] = *(const uint32_t*)&A_s[r * LDS_PAD + k0 + 8 + tid4 * 2];
                    a[mi][3] = *(const uint32_t*)&A_s[(r + 8) * LDS_PAD + k0 + 8 + tid4 * 2];
                }
#pragma unroll
                for (int bp = 0; bp < 2; bp++) {
                    const __half* Bp = B_s[bp];
#pragma unroll
                    for (int ni = 0; ni < 6; ni++) {
                        int nr = n0 + ni * 8 + gid;
                        uint32_t b0 = *(const uint32_t*)&Bp[nr * LDS_PAD + k0 + tid4 * 2];
                        uint32_t b1v = *(const uint32_t*)&Bp[nr * LDS_PAD + k0 + 8 + tid4 * 2];
                        mma_f16(acc[0][ni], a[0], b0, b1v);
                        mma_f16(acc[1][ni], a[1], b0, b1v);
                    }
                }
            }

#pragma unroll
            for (int mi = 0; mi < 2; mi++) {
#pragma unroll
                for (int half = 0; half < 2; half++) {
                    int row = m0 + mi * 16 + gid + half * 8;
                    int node = row0 + row;
#pragma unroll
                    for (int ni = 0; ni < 6; ni++) {
                        int col = nh * 96 + n0 + ni * 8 + tid4 * 2;
                        int t = col >> 6, cin = col & 63;
                        *(__half2*)(z + (size_t)t * NPAD * 64 + (size_t)node * 64 + cin) =
                            __floats2half2_rn(acc[mi][ni][half * 2], acc[mi][ni][half * 2 + 1]);
                    }
                }
            }
        }
    }
}

// ---------------------------------------------------------------------------
// layer-2 aggregation (proven form, unchanged)
// ---------------------------------------------------------------------------
__device__ __forceinline__ void fma_h2(float2& acc, uint32_t zv, float c) {
    float2 f = __half22float2(*reinterpret_cast<__half2*>(&zv));
    acc.x += f.x * c; acc.y += f.y * c;
}

__global__ void __launch_bounds__(256)
k_agg2(const __half* __restrict__ z, const float* __restrict__ dinv,
       const int* __restrict__ off, const int2* __restrict__ csr,
       const float* __restrict__ b2, float* __restrict__ out, int n) {
    int wid = threadIdx.x >> 5, lane = threadIdx.x & 31;
    int node = blockIdx.x * 8 + wid;
    if (node >= n) return;
    int f0 = lane * 2;
    float2 acc = make_float2(
        __ldg(&b2[f0]) + __ldg(&b2[64 + f0]) + __ldg(&b2[128 + f0]),
        __ldg(&b2[f0 + 1]) + __ldg(&b2[64 + f0 + 1]) + __ldg(&b2[128 + f0 + 1]));
#pragma unroll
    for (int t = 0; t < 3; t++) {
        const uint32_t* zt = (const uint32_t*)(z + (size_t)t * NPAD * F2);
        int idx = t * n + node;
        int row_s = __ldg(&off[idx]);
        int row_e = (idx == 3 * n - 1) ? 3 * EMAX : __ldg(&off[idx + 1]);
        float di = __ldg(&dinv[idx]);
        fma_h2(acc, __ldg(zt + (size_t)node * 32 + lane), di * di);
        int e = row_s;
        for (; e + 4 <= row_e; e += 4) {
            int2 p0 = __ldg(&csr[e]);
            int2 p1 = __ldg(&csr[e + 1]);
            int2 p2 = __ldg(&csr[e + 2]);
            int2 p3 = __ldg(&csr[e + 3]);
            uint32_t v0 = __ldg(zt + (size_t)p0.x * 32 + lane);
            uint32_t v1 = __ldg(zt + (size_t)p1.x * 32 + lane);
            uint32_t v2 = __ldg(zt + (size_t)p2.x * 32 + lane);
            uint32_t v3 = __ldg(zt + (size_t)p3.x * 32 + lane);
            fma_h2(acc, v0, __int_as_float(p0.y));
            fma_h2(acc, v1, __int_as_float(p1.y));
            fma_h2(acc, v2, __int_as_float(p2.y));
            fma_h2(acc, v3, __int_as_float(p3.y));
        }
        for (; e < row_e; e++) {
            int2 p = __ldg(&csr[e]);
            fma_h2(acc, __ldg(zt + (size_t)p.x * 32 + lane), __int_as_float(p.y));
        }
    }
    acc.x *= (1.0f / 3.0f); acc.y *= (1.0f / 3.0f);
    ((float2*)out)[(size_t)node * 32 + lane] = acc;
}

// ---------------------------------------------------------------------------
// launch
// ---------------------------------------------------------------------------
static inline int cdiv(long a, long b) { return (int)((a + b - 1) / b); }

extern "C" void kernel_launch(void* const* d_in, const int* in_sizes, int n_in,
                              void* d_out, int out_size) {
    const float* x    = (const float*)d_in[0];
    const int*   edges= (const int*)  d_in[1];
    const float* W1   = (const float*)d_in[2];
    const float* b1   = (const float*)d_in[3];
    const float* W2   = (const float*)d_in[4];
    const float* b2   = (const float*)d_in[5];
    float* out = (float*)d_out;

    const int n = in_sizes[0] / F1;
    const int E = in_sizes[1] / 6;

    cudaFuncSetAttribute(k_gemm_fused, cudaFuncAttributeMaxDynamicSharedMemorySize, GF_SMEM);

    int *hist, *chunk, *off, *cursor, *partial;
    float *dinv;
    int2* csr;
    __half *xh, *y, *z, *w1t0, *w1t1, *w2t0, *w2t1;
    cudaGetSymbolAddress((void**)&hist,    g_hist);
    cudaGetSymbolAddress((void**)&chunk,   g_chunk);
    cudaGetSymbolAddress((void**)&off,     g_off);
    cudaGetSymbolAddress((void**)&cursor,  g_cursor);
    cudaGetSymbolAddress((void**)&partial, g_partial);
    cudaGetSymbolAddress((void**)&dinv,    g_dinv);
    cudaGetSymbolAddress((void**)&csr,     g_csr);
    cudaGetSymbolAddress((void**)&xh,      g_xh);
    cudaGetSymbolAddress((void**)&y,       g_y);
    cudaGetSymbolAddress((void**)&z,       g_z);
    cudaGetSymbolAddress((void**)&w1t0,    g_w1t0);
    cudaGetSymbolAddress((void**)&w1t1,    g_w1t1);
    cudaGetSymbolAddress((void**)&w2t0,    g_w2t0);
    cudaGetSymbolAddress((void**)&w2t1,    g_w2t1);

    const int TB = 256;
    const int tot = 3 * n;
    const int vblocks = cdiv(tot, 1024);
    const int gblocks = NPAD / 128;
    const int nwb = cdiv(n, 8);
    const long e3q = 3L * (E >> 2);
    const long e3o = 3L * (E >> 3);
    const long prep_total = (long)n * 32 + 3L * 128 * 128 + 3L * 128 * 64 + tot;

    // fused prep (x->fp16, weight splits, hist zero)
    k_prep<<<cdiv(prep_total, TB), TB>>>(x, xh, W1, w1t0, w1t1, W2, w2t0, w2t1, hist, n);

    // CSR build
    k_hist8   <<<cdiv(e3o, TB), TB>>>(edges, hist, E, n);
    k_scan1v  <<<vblocks, 256>>>(hist, chunk, partial, tot);
    k_scan2   <<<1, 1024>>>(partial, vblocks);
    k_scan3fv <<<vblocks, 256>>>(chunk, partial, hist, off, cursor, dinv, tot);
    k_permute4<<<cdiv(e3q, TB), TB>>>(edges, dinv, cursor, csr, E, n);

    // layer 1 aggregation (one warp per (relation, node))
    {
        dim3 grid(nwb, 3);
        k_agg1<<<grid, 256>>>(xh, dinv, off, csr, y, n);
    }

    // fused GEMM (layer-1 transform + relu + layer-2 transform, h in smem only)
    k_gemm_fused<<<gblocks, 256, GF_SMEM>>>(y, w1t0, w1t1, b1, w2t0, w2t1, z);

    // layer 2 aggregation
    k_agg2<<<nwb, 256>>>(z, dinv, off, csr, b2, out, n);
}

// round 15
// speedup vs baseline: 1.0020x; 1.0020x over previous
#include <cuda_runtime.h>
#include <cuda_bf16.h>
#include <cuda_fp16.h>
#include <cstdint>

static constexpr int F1 = 128;
static constexpr int F2 = 64;
static constexpr int NMAX = 100000;
static constexpr int NPAD = 100096;       // 782 * 128
static constexpr int EMAX = 1600000;
static constexpr int TOT  = 3 * NMAX;

// ---------------------------------------------------------------------------
// device scratch (zero-initialized at module load; padded rows stay 0 forever)
// ---------------------------------------------------------------------------
__device__ int   g_hist   [TOT];
__device__ int   g_chunk  [TOT];
__device__ int   g_off    [TOT];
__device__ int   g_cursor [TOT];
__device__ int   g_partial[2048];
__device__ float g_dinv   [TOT];
__device__ int2  g_csr    [3 * EMAX];
__device__ __half g_xh  [(size_t)NPAD * F1];       // fp16 x
__device__ __half g_y   [(size_t)3 * NPAD * F1];   // fp16 y
__device__ __half g_z   [(size_t)3 * NPAD * F2];   // fp16 z
__device__ __half g_w1t0[3 * 128 * 128];           // fp16 W1^T hi
__device__ __half g_w1t1[3 * 128 * 128];           // fp16 W1^T lo
__device__ __half g_w2t0[3 * 64 * 128];            // fp16 W2^T hi, stacked [192][128]
__device__ __half g_w2t1[3 * 64 * 128];

// ---------------------------------------------------------------------------
// mma.sync f16
// ---------------------------------------------------------------------------
__device__ __forceinline__ void mma_f16(float* c, const uint32_t* a, uint32_t b0, uint32_t b1) {
    asm volatile("mma.sync.aligned.m16n8k16.row.col.f32.f16.f16.f32 "
        "{%0,%1,%2,%3}, {%4,%5,%6,%7}, {%8,%9}, {%0,%1,%2,%3};"
        : "+f"(c[0]), "+f"(c[1]), "+f"(c[2]), "+f"(c[3])
        : "r"(a[0]), "r"(a[1]), "r"(a[2]), "r"(a[3]), "r"(b0), "r"(b1));
}

// ---------------------------------------------------------------------------
// fused prep: x->fp16 ; W1/W2 fp16 splits ; zero hist
// ---------------------------------------------------------------------------
__device__ __forceinline__ void wsplit_one(const float* __restrict__ W, __half* __restrict__ o0,
                                           __half* __restrict__ o1, int j, int K, int N) {
    int k = j % K;
    int nn = (j / K) % N;
    int t = j / (K * N);
    float w = __ldg(&W[((size_t)t * K + k) * N + nn]);
    __half h0 = __float2half_rn(w);
    float r = w - __half2float(h0);
    size_t o = ((size_t)t * N + nn) * K + k;
    o0[o] = h0;
    o1[o] = __float2half_rn(r);
}

__global__ void k_prep(const float* __restrict__ x, __half* __restrict__ xh,
                       const float* __restrict__ W1, __half* __restrict__ w1t0,
                       __half* __restrict__ w1t1,
                       const float* __restrict__ W2, __half* __restrict__ w2t0,
                       __half* __restrict__ w2t1, int* __restrict__ hist, int n) {
    int i = blockIdx.x * blockDim.x + threadIdx.x;
    int nx = n * 32;
    const int w1n = 3 * 128 * 128, w2n = 3 * 128 * 64;
    if (i < nx) {
        float4 v = __ldg((const float4*)x + i);
        __half2* o = (__half2*)xh + (size_t)i * 2;
        o[0] = __floats2half2_rn(v.x, v.y);
        o[1] = __floats2half2_rn(v.z, v.w);
    } else if (i < nx + w1n) {
        wsplit_one(W1, w1t0, w1t1, i - nx, 128, 128);
    } else if (i < nx + w1n + w2n) {
        wsplit_one(W2, w2t0, w2t1, i - nx - w1n, 128, 64);
    } else if (i < nx + w1n + w2n + 3 * n) {
        hist[i - nx - w1n - w2n] = 0;
    }
}

// ---------------------------------------------------------------------------
// CSR build
// ---------------------------------------------------------------------------
// 8 edges per thread (2x int4)
__global__ void k_hist8(const int* __restrict__ edges, int* __restrict__ hist, int E, int n) {
    int i = blockIdx.x * blockDim.x + threadIdx.x;
    int eo = E >> 3;
    if (i >= 3 * eo) return;
    int t = i / eo, g = i - t * eo;
    const int4* dp = (const int4*)(edges + (size_t)t * 2 * E + E) + g * 2;
    int4 d0 = __ldg(dp);
    int4 d1 = __ldg(dp + 1);
    int* h = hist + t * n;
    atomicAdd(&h[d0.x], 1);
    atomicAdd(&h[d0.y], 1);
    atomicAdd(&h[d0.z], 1);
    atomicAdd(&h[d0.w], 1);
    atomicAdd(&h[d1.x], 1);
    atomicAdd(&h[d1.y], 1);
    atomicAdd(&h[d1.z], 1);
    atomicAdd(&h[d1.w], 1);
}

template<int NW>
__device__ __forceinline__ int block_excl_scan(int v, int tid, int* total) {
    __shared__ int wsum[NW];
    int lane = tid & 31, w = tid >> 5;
    int inc = v;
#pragma unroll
    for (int o = 1; o < 32; o <<= 1) {
        int t = __shfl_up_sync(0xffffffffu, inc, o);
        if (lane >= o) inc += t;
    }
    if (lane == 31) wsum[w] = inc;
    __syncthreads();
    if (w == 0) {
        int s = (lane < NW) ? wsum[lane] : 0;
#pragma unroll
        for (int o = 1; o < NW; o <<= 1) {
            int t = __shfl_up_sync(0xffffffffu, s, o);
            if (lane >= o) s += t;
        }
        if (lane < NW) wsum[lane] = s;
    }
    __syncthreads();
    int wbase = (w == 0) ? 0 : wsum[w - 1];
    *total = wsum[NW - 1];
    __syncthreads();
    return wbase + inc - v;
}

// scan1: 4 elements per thread (1024 per block)
__global__ void k_scan1v(const int* __restrict__ in, int* __restrict__ chunk,
                         int* __restrict__ partial, int total) {
    int tid = threadIdx.x;
    int base = blockIdx.x * 1024 + tid * 4;
    int v0 = 0, v1 = 0, v2 = 0, v3 = 0;
    if (base + 3 < total) {
        int4 v = *(const int4*)(in + base);
        v0 = v.x; v1 = v.y; v2 = v.z; v3 = v.w;
    } else if (base < total) {
        v0 = in[base];
        if (base + 1 < total) v1 = in[base + 1];
        if (base + 2 < total) v2 = in[base + 2];
    }
    int tsum;
    int ex = block_excl_scan<8>(v0 + v1 + v2 + v3, tid, &tsum);
    if (base + 3 < total) {
        int4 o = make_int4(ex, ex + v0, ex + v0 + v1, ex + v0 + v1 + v2);
        *(int4*)(chunk + base) = o;
    } else if (base < total) {
        chunk[base] = ex;
        if (base + 1 < total) chunk[base + 1] = ex + v0;
        if (base + 2 < total) chunk[base + 2] = ex + v0 + v1;
    }
    if (tid == 0) partial[blockIdx.x] = tsum;
}
__global__ void k_scan2(int* __restrict__ partial, int nblocks) {
    __shared__ int running;
    int tid = threadIdx.x;
    if (tid == 0) running = 0;
    __syncthreads();
    for (int base = 0; base < nblocks; base += 1024) {
        int i = base + tid;
        int v = (i < nblocks) ? partial[i] : 0;
        int tsum;
        int ex = block_excl_scan<32>(v, tid, &tsum);
        if (i < nblocks) partial[i] = ex + running;
        __syncthreads();
        if (tid == 0) running += tsum;
        __syncthreads();
    }
}
// scan3: 4 elements per thread; fused off/cursor/dinv
__global__ void k_scan3fv(const int* __restrict__ chunk, const int* __restrict__ partial,
                          const int* __restrict__ hist, int* __restrict__ off,
                          int* __restrict__ cursor, float* __restrict__ dinv, int total) {
    int base = blockIdx.x * 1024 + threadIdx.x * 4;
    int pb = partial[blockIdx.x];
    if (base + 3 < total) {
        int4 c = *(const int4*)(chunk + base);
        int4 h = *(const int4*)(hist + base);
        int4 o = make_int4(c.x + pb, c.y + pb, c.z + pb, c.w + pb);
        *(int4*)(off + base) = o;
        *(int4*)(cursor + base) = o;
        float4 d = make_float4(rsqrtf((float)h.x + 1.0f), rsqrtf((float)h.y + 1.0f),
                               rsqrtf((float)h.z + 1.0f), rsqrtf((float)h.w + 1.0f));
        *(float4*)(dinv + base) = d;
    } else {
        for (int j = 0; j < 4; j++) {
            int i = base + j;
            if (i < total) {
                int v = chunk[i] + pb;
                off[i] = v;
                cursor[i] = v;
                dinv[i] = rsqrtf((float)hist[i] + 1.0f);
            }
        }
    }
}
__global__ void k_permute4(const int* __restrict__ edges, const float* __restrict__ dinv,
                           int* __restrict__ cursor, int2* __restrict__ csr, int E, int n) {
    int i = blockIdx.x * blockDim.x + threadIdx.x;
    int eq = E >> 2;
    if (i >= 3 * eq) return;
    int t = i / eq, g = i - t * eq;
    const int* base = edges + (size_t)t * 2 * E;
    int4 s4 = __ldg((const int4*)base + g);
    int4 d4 = __ldg((const int4*)(base + E) + g);
    const float* dv = dinv + t * n;
    int* cur = cursor + t * n;
#pragma unroll
    for (int j = 0; j < 4; j++) {
        int s = (j == 0) ? s4.x : (j == 1) ? s4.y : (j == 2) ? s4.z : s4.w;
        int d = (j == 0) ? d4.x : (j == 1) ? d4.y : (j == 2) ? d4.z : d4.w;
        int pos = atomicAdd(&cur[d], 1);
        float c = __ldg(&dv[s]) * __ldg(&dv[d]);
        csr[pos] = make_int2(s, __float_as_int(c));
    }
}

// ---------------------------------------------------------------------------
// layer-1 aggregation (round-10/12 winner form): one warp per (relation,node)
// ---------------------------------------------------------------------------
__device__ __forceinline__ void fma_h4(float4& acc, uint2 xv, float c) {
    float2 f0 = __half22float2(*reinterpret_cast<__half2*>(&xv.x));
    float2 f1 = __half22float2(*reinterpret_cast<__half2*>(&xv.y));
    acc.x += f0.x * c; acc.y += f0.y * c; acc.z += f1.x * c; acc.w += f1.y * c;
}

__global__ void __launch_bounds__(256)
k_agg1(const __half* __restrict__ xh, const float* __restrict__ dinv,
       const int* __restrict__ off, const int2* __restrict__ csr,
       __half* __restrict__ y, int n) {
    int wid = threadIdx.x >> 5, lane = threadIdx.x & 31;
    int node = blockIdx.x * 8 + wid;
    if (node >= n) return;
    int t = blockIdx.y;
    int idx = t * n + node;
    int row_s = __ldg(&off[idx]);
    int row_e = (idx == 3 * n - 1) ? 3 * EMAX : __ldg(&off[idx + 1]);
    float di = __ldg(&dinv[idx]);
    const uint2* xv = (const uint2*)xh;
    float4 acc = make_float4(0.f, 0.f, 0.f, 0.f);
    fma_h4(acc, __ldg(xv + (size_t)node * 32 + lane), di * di);
    int e = row_s;
    for (; e + 4 <= row_e; e += 4) {
        int2 p0 = __ldg(&csr[e]);
        int2 p1 = __ldg(&csr[e + 1]);
        int2 p2 = __ldg(&csr[e + 2]);
        int2 p3 = __ldg(&csr[e + 3]);
        uint2 v0 = __ldg(xv + (size_t)p0.x * 32 + lane);
        uint2 v1 = __ldg(xv + (size_t)p1.x * 32 + lane);
        uint2 v2 = __ldg(xv + (size_t)p2.x * 32 + lane);
        uint2 v3 = __ldg(xv + (size_t)p3.x * 32 + lane);
        fma_h4(acc, v0, __int_as_float(p0.y));
        fma_h4(acc, v1, __int_as_float(p1.y));
        fma_h4(acc, v2, __int_as_float(p2.y));
        fma_h4(acc, v3, __int_as_float(p3.y));
    }
    for (; e < row_e; e++) {
        int2 p = __ldg(&csr[e]);
        fma_h4(acc, __ldg(xv + (size_t)p.x * 32 + lane), __int_as_float(p.y));
    }
    size_t base = ((size_t)t * NPAD + node) * 64 + lane * 2;
    ((__half2*)y)[base]     = __floats2half2_rn(acc.x, acc.y);
    ((__half2*)y)[base + 1] = __floats2half2_rn(acc.z, acc.w);
}

// ---------------------------------------------------------------------------
// FUSED GEMM v2 (round-12 winner, exact): 104960 B smem, no minBlocks cap
// ---------------------------------------------------------------------------
static constexpr int LDS_PAD = 136;
static constexpr int GF_SMEM = 104448 + 512;
__global__ void __launch_bounds__(256)
k_gemm_fused(const __half* __restrict__ y, const __half* __restrict__ w10,
             const __half* __restrict__ w11, const float* __restrict__ b1,
             const __half* __restrict__ w20, const __half* __restrict__ w21,
             __half* __restrict__ z) {
    extern __shared__ char smem[];
    __half* A_s = (__half*)smem;
    float* sumb = (float*)(smem + 104448);

    const int tid = threadIdx.x, wid = tid >> 5, lane = tid & 31;
    const int gid = lane >> 2, tid4 = lane & 3;
    const int row0 = blockIdx.x * 128;
    const int m0 = (wid & 3) * 32;

    if (tid < 128) sumb[tid] = __ldg(&b1[tid]) + __ldg(&b1[128 + tid]) + __ldg(&b1[256 + tid]);

    // ---------------- phase 1: h tile into A_s ----------------
    {
        __half* B_s[2] = { (__half*)(smem + 34816), (__half*)(smem + 69632) };
        const int n0 = (wid >> 2) * 64;

        float acc[2][8][4];
#pragma unroll
        for (int mi = 0; mi < 2; mi++)
#pragma unroll
            for (int ni = 0; ni < 8; ni++)
#pragma unroll
                for (int c = 0; c < 4; c++) acc[mi][ni][c] = 0.0f;

        for (int t = 0; t < 3; t++) {
            const __half* Ag  = y   + ((size_t)t * NPAD + row0) * 128;
            const __half* Bg0 = w10 + (size_t)t * 16384;
            const __half* Bg1 = w11 + (size_t)t * 16384;
            __syncthreads();
#pragma unroll
            for (int i = tid; i < 2048; i += 256) {
                int r = i >> 4, c = i & 15;
                *(uint4*)&A_s[r * LDS_PAD + c * 8]    = *(const uint4*)(Ag  + (size_t)r * 128 + c * 8);
                *(uint4*)&B_s[0][r * LDS_PAD + c * 8] = *(const uint4*)(Bg0 + (size_t)r * 128 + c * 8);
                *(uint4*)&B_s[1][r * LDS_PAD + c * 8] = *(const uint4*)(Bg1 + (size_t)r * 128 + c * 8);
            }
            __syncthreads();
#pragma unroll
            for (int ks = 0; ks < 8; ks++) {
                int k0 = ks * 16;
                uint32_t a[2][4];
#pragma unroll
                for (int mi = 0; mi < 2; mi++) {
                    int r = m0 + mi * 16 + gid;
                    a[mi][0] = *(const uint32_t*)&A_s[r * LDS_PAD + k0 + tid4 * 2];
                    a[mi][1] = *(const uint32_t*)&A_s[(r + 8) * LDS_PAD + k0 + tid4 * 2];
                    a[mi][2] = *(const uint32_t*)&A_s[r * LDS_PAD + k0 + 8 + tid4 * 2];
                    a[mi][3] = *(const uint32_t*)&A_s[(r + 8) * LDS_PAD + k0 + 8 + tid4 * 2];
                }
#pragma unroll
                for (int bp = 0; bp < 2; bp++) {
                    const __half* Bp = B_s[bp];
#pragma unroll
                    for (int ni = 0; ni < 8; ni++) {
                        int nr = n0 + ni * 8 + gid;
                        uint32_t b0 = *(const uint32_t*)&Bp[nr * LDS_PAD + k0 + tid4 * 2];
                        uint32_t b1v = *(const uint32_t*)&Bp[nr * LDS_PAD + k0 + 8 + tid4 * 2];
                        mma_f16(acc[0][ni], a[0], b0, b1v);
                        mma_f16(acc[1][ni], a[1], b0, b1v);
                    }
                }
            }
        }
        __syncthreads();   // all A_s/B_s reads of phase 1 done; write h tile
#pragma unroll
        for (int mi = 0; mi < 2; mi++) {
#pragma unroll
            for (int half = 0; half < 2; half++) {
                int row = m0 + mi * 16 + gid + half * 8;
#pragma unroll
                for (int ni = 0; ni < 8; ni++) {
                    int col = n0 + ni * 8 + tid4 * 2;
                    float f0 = fmaxf((acc[mi][ni][half * 2]     + sumb[col])     * (1.0f / 3.0f), 0.0f);
                    float f1 = fmaxf((acc[mi][ni][half * 2 + 1] + sumb[col + 1]) * (1.0f / 3.0f), 0.0f);
                    *(__half2*)&A_s[row * LDS_PAD + col] = __floats2half2_rn(f0, f1);
                }
            }
        }
    }

    // ---------------- phase 2: z = h @ W2^T in two N-halves ----------------
    {
        __half* B_s[2] = { (__half*)(smem + 34816), (__half*)(smem + 60928) };
        const int n0 = (wid >> 2) * 48;

        for (int nh = 0; nh < 2; nh++) {
            const __half* Bg0 = w20 + (size_t)nh * 96 * 128;
            const __half* Bg1 = w21 + (size_t)nh * 96 * 128;
            __syncthreads();
#pragma unroll
            for (int i = tid; i < 1536; i += 256) {
                int r = i >> 4, c = i & 15;
                *(uint4*)&B_s[0][r * LDS_PAD + c * 8] = *(const uint4*)(Bg0 + (size_t)r * 128 + c * 8);
                *(uint4*)&B_s[1][r * LDS_PAD + c * 8] = *(const uint4*)(Bg1 + (size_t)r * 128 + c * 8);
            }
            __syncthreads();

            float acc[2][6][4];
#pragma unroll
            for (int mi = 0; mi < 2; mi++)
#pragma unroll
                for (int ni = 0; ni < 6; ni++)
#pragma unroll
                    for (int c = 0; c < 4; c++) acc[mi][ni][c] = 0.0f;

#pragma unroll
            for (int ks = 0; ks < 8; ks++) {
                int k0 = ks * 16;
                uint32_t a[2][4];
#pragma unroll
                for (int mi = 0; mi < 2; mi++) {
                    int r = m0 + mi * 16 + gid;
                    a[mi][0] = *(const uint32_t*)&A_s[r * LDS_PAD + k0 + tid4 * 2];
                    a[mi][1] = *(const uint32_t*)&A_s[(r + 8) * LDS_PAD + k0 + tid4 * 2];
                    a[mi][2] = *(const uint32_t*)&A_s[r * LDS_PAD + k0 + 8 + tid4 * 2];
                    a[mi][3] = *(const uint32_t*)&A_s[(r + 8) * LDS_PAD + k0 + 8 + tid4 * 2];
                }
#pragma unroll
                for (int bp = 0; bp < 2; bp++) {
                    const __half* Bp = B_s[bp];
#pragma unroll
                    for (int ni = 0; ni < 6; ni++) {
                        int nr = n0 + ni * 8 + gid;
                        uint32_t b0 = *(const uint32_t*)&Bp[nr * LDS_PAD + k0 + tid4 * 2];
                        uint32_t b1v = *(const uint32_t*)&Bp[nr * LDS_PAD + k0 + 8 + tid4 * 2];
                        mma_f16(acc[0][ni], a[0], b0, b1v);
                        mma_f16(acc[1][ni], a[1], b0, b1v);
                    }
                }
            }

#pragma unroll
            for (int mi = 0; mi < 2; mi++) {
#pragma unroll
                for (int half = 0; half < 2; half++) {
                    int row = m0 + mi * 16 + gid + half * 8;
                    int node = row0 + row;
#pragma unroll
                    for (int ni = 0; ni < 6; ni++) {
                        int col = nh * 96 + n0 + ni * 8 + tid4 * 2;
                        int t = col >> 6, cin = col & 63;
                        *(__half2*)(z + (size_t)t * NPAD * 64 + (size_t)node * 64 + cin) =
                            __floats2half2_rn(acc[mi][ni][half * 2], acc[mi][ni][half * 2 + 1]);
                    }
                }
            }
        }
    }
}

// ---------------------------------------------------------------------------
// layer-2 aggregation (proven form, unchanged)
// ---------------------------------------------------------------------------
__device__ __forceinline__ void fma_h2(float2& acc, uint32_t zv, float c) {
    float2 f = __half22float2(*reinterpret_cast<__half2*>(&zv));
    acc.x += f.x * c; acc.y += f.y * c;
}

__global__ void __launch_bounds__(256)
k_agg2(const __half* __restrict__ z, const float* __restrict__ dinv,
       const int* __restrict__ off, const int2* __restrict__ csr,
       const float* __restrict__ b2, float* __restrict__ out, int n) {
    int wid = threadIdx.x >> 5, lane = threadIdx.x & 31;
    int node = blockIdx.x * 8 + wid;
    if (node >= n) return;
    int f0 = lane * 2;
    float2 acc = make_float2(
        __ldg(&b2[f0]) + __ldg(&b2[64 + f0]) + __ldg(&b2[128 + f0]),
        __ldg(&b2[f0 + 1]) + __ldg(&b2[64 + f0 + 1]) + __ldg(&b2[128 + f0 + 1]));
#pragma unroll
    for (int t = 0; t < 3; t++) {
        const uint32_t* zt = (const uint32_t*)(z + (size_t)t * NPAD * F2);
        int idx = t * n + node;
        int row_s = __ldg(&off[idx]);
        int row_e = (idx == 3 * n - 1) ? 3 * EMAX : __ldg(&off[idx + 1]);
        float di = __ldg(&dinv[idx]);
        fma_h2(acc, __ldg(zt + (size_t)node * 32 + lane), di * di);
        int e = row_s;
        for (; e + 4 <= row_e; e += 4) {
            int2 p0 = __ldg(&csr[e]);
            int2 p1 = __ldg(&csr[e + 1]);
            int2 p2 = __ldg(&csr[e + 2]);
            int2 p3 = __ldg(&csr[e + 3]);
            uint32_t v0 = __ldg(zt + (size_t)p0.x * 32 + lane);
            uint32_t v1 = __ldg(zt + (size_t)p1.x * 32 + lane);
            uint32_t v2 = __ldg(zt + (size_t)p2.x * 32 + lane);
            uint32_t v3 = __ldg(zt + (size_t)p3.x * 32 + lane);
            fma_h2(acc, v0, __int_as_float(p0.y));
            fma_h2(acc, v1, __int_as_float(p1.y));
            fma_h2(acc, v2, __int_as_float(p2.y));
            fma_h2(acc, v3, __int_as_float(p3.y));
        }
        for (; e < row_e; e++) {
            int2 p = __ldg(&csr[e]);
            fma_h2(acc, __ldg(zt + (size_t)p.x * 32 + lane), __int_as_float(p.y));
        }
    }
    acc.x *= (1.0f / 3.0f); acc.y *= (1.0f / 3.0f);
    ((float2*)out)[(size_t)node * 32 + lane] = acc;
}

// ---------------------------------------------------------------------------
// launch
// ---------------------------------------------------------------------------
static inline int cdiv(long a, long b) { return (int)((a + b - 1) / b); }

extern "C" void kernel_launch(void* const* d_in, const int* in_sizes, int n_in,
                              void* d_out, int out_size) {
    const float* x    = (const float*)d_in[0];
    const int*   edges= (const int*)  d_in[1];
    const float* W1   = (const float*)d_in[2];
    const float* b1   = (const float*)d_in[3];
    const float* W2   = (const float*)d_in[4];
    const float* b2   = (const float*)d_in[5];
    float* out = (float*)d_out;

    const int n = in_sizes[0] / F1;
    const int E = in_sizes[1] / 6;

    cudaFuncSetAttribute(k_gemm_fused, cudaFuncAttributeMaxDynamicSharedMemorySize, GF_SMEM);

    int *hist, *chunk, *off, *cursor, *partial;
    float *dinv;
    int2* csr;
    __half *xh, *y, *z, *w1t0, *w1t1, *w2t0, *w2t1;
    cudaGetSymbolAddress((void**)&hist,    g_hist);
    cudaGetSymbolAddress((void**)&chunk,   g_chunk);
    cudaGetSymbolAddress((void**)&off,     g_off);
    cudaGetSymbolAddress((void**)&cursor,  g_cursor);
    cudaGetSymbolAddress((void**)&partial, g_partial);
    cudaGetSymbolAddress((void**)&dinv,    g_dinv);
    cudaGetSymbolAddress((void**)&csr,     g_csr);
    cudaGetSymbolAddress((void**)&xh,      g_xh);
    cudaGetSymbolAddress((void**)&y,       g_y);
    cudaGetSymbolAddress((void**)&z,       g_z);
    cudaGetSymbolAddress((void**)&w1t0,    g_w1t0);
    cudaGetSymbolAddress((void**)&w1t1,    g_w1t1);
    cudaGetSymbolAddress((void**)&w2t0,    g_w2t0);
    cudaGetSymbolAddress((void**)&w2t1,    g_w2t1);

    const int TB = 256;
    const int tot = 3 * n;
    const int vblocks = cdiv(tot, 1024);
    const int gblocks = NPAD / 128;
    const int nwb = cdiv(n, 8);
    const long e3q = 3L * (E >> 2);
    const long e3o = 3L * (E >> 3);
    const long prep_total = (long)n * 32 + 3L * 128 * 128 + 3L * 128 * 64 + tot;

    // fused prep (x->fp16, weight splits, hist zero)
    k_prep<<<cdiv(prep_total, TB), TB>>>(x, xh, W1, w1t0, w1t1, W2, w2t0, w2t1, hist, n);

    // CSR build
    k_hist8   <<<cdiv(e3o, TB), TB>>>(edges, hist, E, n);
    k_scan1v  <<<vblocks, 256>>>(hist, chunk, partial, tot);
    k_scan2   <<<1, 1024>>>(partial, vblocks);
    k_scan3fv <<<vblocks, 256>>>(chunk, partial, hist, off, cursor, dinv, tot);
    k_permute4<<<cdiv(e3q, TB), TB>>>(edges, dinv, cursor, csr, E, n);

    // layer 1 aggregation (one warp per (relation, node))
    {
        dim3 grid(nwb, 3);
        k_agg1<<<grid, 256>>>(xh, dinv, off, csr, y, n);
    }

    // fused GEMM (layer-1 transform + relu + layer-2 transform, h in smem only)
    k_gemm_fused<<<gblocks, 256, GF_SMEM>>>(y, w1t0, w1t1, b1, w2t0, w2t1, z);

    // layer 2 aggregation
    k_agg2<<<nwb, 256>>>(z, dinv, off, csr, b2, out, n);
}

// round 16
// speedup vs baseline: 1.0047x; 1.0027x over previous
#include <cuda_runtime.h>
#include <cuda_bf16.h>
#include <cuda_fp16.h>
#include <cstdint>

static constexpr int F1 = 128;
static constexpr int F2 = 64;
static constexpr int NMAX = 100000;
static constexpr int NPAD = 100096;       // 782 * 128
static constexpr int EMAX = 1600000;
static constexpr int TOT  = 3 * NMAX;

// ---------------------------------------------------------------------------
// device scratch (zero-initialized at module load; padded rows stay 0 forever)
// ---------------------------------------------------------------------------
__device__ int   g_hist   [TOT];
__device__ int   g_chunk  [TOT];
__device__ int   g_off    [TOT];
__device__ int   g_cursor [TOT];
__device__ int   g_partial[2048];
__device__ float g_dinv   [TOT];
__device__ int2  g_csr    [3 * EMAX];
__device__ __half g_xh  [(size_t)NPAD * F1];       // fp16 x
__device__ __half g_y   [(size_t)3 * NPAD * F1];   // fp16 y
__device__ __half g_z   [(size_t)3 * NPAD * F2];   // fp16 z
__device__ __half g_w1t0[3 * 128 * 128];           // fp16 W1^T hi
__device__ __half g_w1t1[3 * 128 * 128];           // fp16 W1^T lo
__device__ __half g_w2t0[3 * 64 * 128];            // fp16 W2^T hi, stacked [192][128]
__device__ __half g_w2t1[3 * 64 * 128];

// ---------------------------------------------------------------------------
// mma.sync f16
// ---------------------------------------------------------------------------
__device__ __forceinline__ void mma_f16(float* c, const uint32_t* a, uint32_t b0, uint32_t b1) {
    asm volatile("mma.sync.aligned.m16n8k16.row.col.f32.f16.f16.f32 "
        "{%0,%1,%2,%3}, {%4,%5,%6,%7}, {%8,%9}, {%0,%1,%2,%3};"
        : "+f"(c[0]), "+f"(c[1]), "+f"(c[2]), "+f"(c[3])
        : "r"(a[0]), "r"(a[1]), "r"(a[2]), "r"(a[3]), "r"(b0), "r"(b1));
}

// ---------------------------------------------------------------------------
// fused prep: x->fp16 ; W1/W2 fp16 splits ; zero hist
// ---------------------------------------------------------------------------
__device__ __forceinline__ void wsplit_one(const float* __restrict__ W, __half* __restrict__ o0,
                                           __half* __restrict__ o1, int j, int K, int N) {
    int k = j % K;
    int nn = (j / K) % N;
    int t = j / (K * N);
    float w = __ldg(&W[((size_t)t * K + k) * N + nn]);
    __half h0 = __float2half_rn(w);
    float r = w - __half2float(h0);
    size_t o = ((size_t)t * N + nn) * K + k;
    o0[o] = h0;
    o1[o] = __float2half_rn(r);
}

__global__ void k_prep(const float* __restrict__ x, __half* __restrict__ xh,
                       const float* __restrict__ W1, __half* __restrict__ w1t0,
                       __half* __restrict__ w1t1,
                       const float* __restrict__ W2, __half* __restrict__ w2t0,
                       __half* __restrict__ w2t1, int* __restrict__ hist, int n) {
    int i = blockIdx.x * blockDim.x + threadIdx.x;
    int nx = n * 32;
    const int w1n = 3 * 128 * 128, w2n = 3 * 128 * 64;
    if (i < nx) {
        float4 v = __ldg((const float4*)x + i);
        __half2* o = (__half2*)xh + (size_t)i * 2;
        o[0] = __floats2half2_rn(v.x, v.y);
        o[1] = __floats2half2_rn(v.z, v.w);
    } else if (i < nx + w1n) {
        wsplit_one(W1, w1t0, w1t1, i - nx, 128, 128);
    } else if (i < nx + w1n + w2n) {
        wsplit_one(W2, w2t0, w2t1, i - nx - w1n, 128, 64);
    } else if (i < nx + w1n + w2n + 3 * n) {
        hist[i - nx - w1n - w2n] = 0;
    }
}

// ---------------------------------------------------------------------------
// CSR build
// ---------------------------------------------------------------------------
__global__ void k_hist4(const int* __restrict__ edges, int* __restrict__ hist, int E, int n) {
    int i = blockIdx.x * blockDim.x + threadIdx.x;
    int eq = E >> 2;
    if (i >= 3 * eq) return;
    int t = i / eq, g = i - t * eq;
    int4 d = __ldg((const int4*)(edges + (size_t)t * 2 * E + E) + g);
    int* h = hist + t * n;
    atomicAdd(&h[d.x], 1);
    atomicAdd(&h[d.y], 1);
    atomicAdd(&h[d.z], 1);
    atomicAdd(&h[d.w], 1);
}

template<int NW>
__device__ __forceinline__ int block_excl_scan(int v, int tid, int* total) {
    __shared__ int wsum[NW];
    int lane = tid & 31, w = tid >> 5;
    int inc = v;
#pragma unroll
    for (int o = 1; o < 32; o <<= 1) {
        int t = __shfl_up_sync(0xffffffffu, inc, o);
        if (lane >= o) inc += t;
    }
    if (lane == 31) wsum[w] = inc;
    __syncthreads();
    if (w == 0) {
        int s = (lane < NW) ? wsum[lane] : 0;
#pragma unroll
        for (int o = 1; o < NW; o <<= 1) {
            int t = __shfl_up_sync(0xffffffffu, s, o);
            if (lane >= o) s += t;
        }
        if (lane < NW) wsum[lane] = s;
    }
    __syncthreads();
    int wbase = (w == 0) ? 0 : wsum[w - 1];
    *total = wsum[NW - 1];
    __syncthreads();
    return wbase + inc - v;
}

// scan1: 4 elements per thread (1024 per block)
__global__ void k_scan1v(const int* __restrict__ in, int* __restrict__ chunk,
                         int* __restrict__ partial, int total) {
    int tid = threadIdx.x;
    int base = blockIdx.x * 1024 + tid * 4;
    int v0 = 0, v1 = 0, v2 = 0, v3 = 0;
    if (base + 3 < total) {
        int4 v = *(const int4*)(in + base);
        v0 = v.x; v1 = v.y; v2 = v.z; v3 = v.w;
    } else if (base < total) {
        v0 = in[base];
        if (base + 1 < total) v1 = in[base + 1];
        if (base + 2 < total) v2 = in[base + 2];
    }
    int tsum;
    int ex = block_excl_scan<8>(v0 + v1 + v2 + v3, tid, &tsum);
    if (base + 3 < total) {
        int4 o = make_int4(ex, ex + v0, ex + v0 + v1, ex + v0 + v1 + v2);
        *(int4*)(chunk + base) = o;
    } else if (base < total) {
        chunk[base] = ex;
        if (base + 1 < total) chunk[base + 1] = ex + v0;
        if (base + 2 < total) chunk[base + 2] = ex + v0 + v1;
    }
    if (tid == 0) partial[blockIdx.x] = tsum;
}
__global__ void k_scan2(int* __restrict__ partial, int nblocks) {
    __shared__ int running;
    int tid = threadIdx.x;
    if (tid == 0) running = 0;
    __syncthreads();
    for (int base = 0; base < nblocks; base += 1024) {
        int i = base + tid;
        int v = (i < nblocks) ? partial[i] : 0;
        int tsum;
        int ex = block_excl_scan<32>(v, tid, &tsum);
        if (i < nblocks) partial[i] = ex + running;
        __syncthreads();
        if (tid == 0) running += tsum;
        __syncthreads();
    }
}
// scan3: 4 elements per thread; fused off/cursor/dinv
__global__ void k_scan3fv(const int* __restrict__ chunk, const int* __restrict__ partial,
                          const int* __restrict__ hist, int* __restrict__ off,
                          int* __restrict__ cursor, float* __restrict__ dinv, int total) {
    int base = blockIdx.x * 1024 + threadIdx.x * 4;
    int pb = partial[blockIdx.x];
    if (base + 3 < total) {
        int4 c = *(const int4*)(chunk + base);
        int4 h = *(const int4*)(hist + base);
        int4 o = make_int4(c.x + pb, c.y + pb, c.z + pb, c.w + pb);
        *(int4*)(off + base) = o;
        *(int4*)(cursor + base) = o;
        float4 d = make_float4(rsqrtf((float)h.x + 1.0f), rsqrtf((float)h.y + 1.0f),
                               rsqrtf((float)h.z + 1.0f), rsqrtf((float)h.w + 1.0f));
        *(float4*)(dinv + base) = d;
    } else {
        for (int j = 0; j < 4; j++) {
            int i = base + j;
            if (i < total) {
                int v = chunk[i] + pb;
                off[i] = v;
                cursor[i] = v;
                dinv[i] = rsqrtf((float)hist[i] + 1.0f);
            }
        }
    }
}
__global__ void k_permute4(const int* __restrict__ edges, const float* __restrict__ dinv,
                           int* __restrict__ cursor, int2* __restrict__ csr, int E, int n) {
    int i = blockIdx.x * blockDim.x + threadIdx.x;
    int eq = E >> 2;
    if (i >= 3 * eq) return;
    int t = i / eq, g = i - t * eq;
    const int* base = edges + (size_t)t * 2 * E;
    int4 s4 = __ldg((const int4*)base + g);
    int4 d4 = __ldg((const int4*)(base + E) + g);
    const float* dv = dinv + t * n;
    int* cur = cursor + t * n;
#pragma unroll
    for (int j = 0; j < 4; j++) {
        int s = (j == 0) ? s4.x : (j == 1) ? s4.y : (j == 2) ? s4.z : s4.w;
        int d = (j == 0) ? d4.x : (j == 1) ? d4.y : (j == 2) ? d4.z : d4.w;
        int pos = atomicAdd(&cur[d], 1);
        float c = __ldg(&dv[s]) * __ldg(&dv[d]);
        csr[pos] = make_int2(s, __float_as_int(c));
    }
}

// ---------------------------------------------------------------------------
// layer-1 aggregation (winner form): one warp per (relation,node)
// ---------------------------------------------------------------------------
__device__ __forceinline__ void fma_h4(float4& acc, uint2 xv, float c) {
    float2 f0 = __half22float2(*reinterpret_cast<__half2*>(&xv.x));
    float2 f1 = __half22float2(*reinterpret_cast<__half2*>(&xv.y));
    acc.x += f0.x * c; acc.y += f0.y * c; acc.z += f1.x * c; acc.w += f1.y * c;
}

__global__ void __launch_bounds__(256)
k_agg1(const __half* __restrict__ xh, const float* __restrict__ dinv,
       const int* __restrict__ off, const int2* __restrict__ csr,
       __half* __restrict__ y, int n) {
    int wid = threadIdx.x >> 5, lane = threadIdx.x & 31;
    int node = blockIdx.x * 8 + wid;
    if (node >= n) return;
    int t = blockIdx.y;
    int idx = t * n + node;
    int row_s = __ldg(&off[idx]);
    int row_e = (idx == 3 * n - 1) ? 3 * EMAX : __ldg(&off[idx + 1]);
    float di = __ldg(&dinv[idx]);
    const uint2* xv = (const uint2*)xh;
    float4 acc = make_float4(0.f, 0.f, 0.f, 0.f);
    fma_h4(acc, __ldg(xv + (size_t)node * 32 + lane), di * di);
    int e = row_s;
    for (; e + 4 <= row_e; e += 4) {
        int2 p0 = __ldg(&csr[e]);
        int2 p1 = __ldg(&csr[e + 1]);
        int2 p2 = __ldg(&csr[e + 2]);
        int2 p3 = __ldg(&csr[e + 3]);
        uint2 v0 = __ldg(xv + (size_t)p0.x * 32 + lane);
        uint2 v1 = __ldg(xv + (size_t)p1.x * 32 + lane);
        uint2 v2 = __ldg(xv + (size_t)p2.x * 32 + lane);
        uint2 v3 = __ldg(xv + (size_t)p3.x * 32 + lane);
        fma_h4(acc, v0, __int_as_float(p0.y));
        fma_h4(acc, v1, __int_as_float(p1.y));
        fma_h4(acc, v2, __int_as_float(p2.y));
        fma_h4(acc, v3, __int_as_float(p3.y));
    }
    for (; e < row_e; e++) {
        int2 p = __ldg(&csr[e]);
        fma_h4(acc, __ldg(xv + (size_t)p.x * 32 + lane), __int_as_float(p.y));
    }
    size_t base = ((size_t)t * NPAD + node) * 64 + lane * 2;
    ((__half2*)y)[base]     = __floats2half2_rn(acc.x, acc.y);
    ((__half2*)y)[base + 1] = __floats2half2_rn(acc.z, acc.w);
}

// ---------------------------------------------------------------------------
// FUSED GEMM v2 (winner, exact): 104960 B smem
// ---------------------------------------------------------------------------
static constexpr int LDS_PAD = 136;
static constexpr int GF_SMEM = 104448 + 512;
__global__ void __launch_bounds__(256)
k_gemm_fused(const __half* __restrict__ y, const __half* __restrict__ w10,
             const __half* __restrict__ w11, const float* __restrict__ b1,
             const __half* __restrict__ w20, const __half* __restrict__ w21,
             __half* __restrict__ z) {
    extern __shared__ char smem[];
    __half* A_s = (__half*)smem;
    float* sumb = (float*)(smem + 104448);

    const int tid = threadIdx.x, wid = tid >> 5, lane = tid & 31;
    const int gid = lane >> 2, tid4 = lane & 3;
    const int row0 = blockIdx.x * 128;
    const int m0 = (wid & 3) * 32;

    if (tid < 128) sumb[tid] = __ldg(&b1[tid]) + __ldg(&b1[128 + tid]) + __ldg(&b1[256 + tid]);

    // ---------------- phase 1: h tile into A_s ----------------
    {
        __half* B_s[2] = { (__half*)(smem + 34816), (__half*)(smem + 69632) };
        const int n0 = (wid >> 2) * 64;

        float acc[2][8][4];
#pragma unroll
        for (int mi = 0; mi < 2; mi++)
#pragma unroll
            for (int ni = 0; ni < 8; ni++)
#pragma unroll
                for (int c = 0; c < 4; c++) acc[mi][ni][c] = 0.0f;

        for (int t = 0; t < 3; t++) {
            const __half* Ag  = y   + ((size_t)t * NPAD + row0) * 128;
            const __half* Bg0 = w10 + (size_t)t * 16384;
            const __half* Bg1 = w11 + (size_t)t * 16384;
            __syncthreads();
#pragma unroll
            for (int i = tid; i < 2048; i += 256) {
                int r = i >> 4, c = i & 15;
                *(uint4*)&A_s[r * LDS_PAD + c * 8]    = *(const uint4*)(Ag  + (size_t)r * 128 + c * 8);
                *(uint4*)&B_s[0][r * LDS_PAD + c * 8] = *(const uint4*)(Bg0 + (size_t)r * 128 + c * 8);
                *(uint4*)&B_s[1][r * LDS_PAD + c * 8] = *(const uint4*)(Bg1 + (size_t)r * 128 + c * 8);
            }
            __syncthreads();
#pragma unroll
            for (int ks = 0; ks < 8; ks++) {
                int k0 = ks * 16;
                uint32_t a[2][4];
#pragma unroll
                for (int mi = 0; mi < 2; mi++) {
                    int r = m0 + mi * 16 + gid;
                    a[mi][0] = *(const uint32_t*)&A_s[r * LDS_PAD + k0 + tid4 * 2];
                    a[mi][1] = *(const uint32_t*)&A_s[(r + 8) * LDS_PAD + k0 + tid4 * 2];
                    a[mi][2] = *(const uint32_t*)&A_s[r * LDS_PAD + k0 + 8 + tid4 * 2];
                    a[mi][3] = *(const uint32_t*)&A_s[(r + 8) * LDS_PAD + k0 + 8 + tid4 * 2];
                }
#pragma unroll
                for (int bp = 0; bp < 2; bp++) {
                    const __half* Bp = B_s[bp];
#pragma unroll
                    for (int ni = 0; ni < 8; ni++) {
                        int nr = n0 + ni * 8 + gid;
                        uint32_t b0 = *(const uint32_t*)&Bp[nr * LDS_PAD + k0 + tid4 * 2];
                        uint32_t b1v = *(const uint32_t*)&Bp[nr * LDS_PAD + k0 + 8 + tid4 * 2];
                        mma_f16(acc[0][ni], a[0], b0, b1v);
                        mma_f16(acc[1][ni], a[1], b0, b1v);
                    }
                }
            }
        }
        __syncthreads();   // all A_s/B_s reads of phase 1 done; write h tile
#pragma unroll
        for (int mi = 0; mi < 2; mi++) {
#pragma unroll
            for (int half = 0; half < 2; half++) {
                int row = m0 + mi * 16 + gid + half * 8;
#pragma unroll
                for (int ni = 0; ni < 8; ni++) {
                    int col = n0 + ni * 8 + tid4 * 2;
                    float f0 = fmaxf((acc[mi][ni][half * 2]     + sumb[col])     * (1.0f / 3.0f), 0.0f);
                    float f1 = fmaxf((acc[mi][ni][half * 2 + 1] + sumb[col + 1]) * (1.0f / 3.0f), 0.0f);
                    *(__half2*)&A_s[row * LDS_PAD + col] = __floats2half2_rn(f0, f1);
                }
            }
        }
    }

    // ---------------- phase 2: z = h @ W2^T in two N-halves ----------------
    {
        __half* B_s[2] = { (__half*)(smem + 34816), (__half*)(smem + 60928) };
        const int n0 = (wid >> 2) * 48;

        for (int nh = 0; nh < 2; nh++) {
            const __half* Bg0 = w20 + (size_t)nh * 96 * 128;
            const __half* Bg1 = w21 + (size_t)nh * 96 * 128;
            __syncthreads();
#pragma unroll
            for (int i = tid; i < 1536; i += 256) {
                int r = i >> 4, c = i & 15;
                *(uint4*)&B_s[0][r * LDS_PAD + c * 8] = *(const uint4*)(Bg0 + (size_t)r * 128 + c * 8);
                *(uint4*)&B_s[1][r * LDS_PAD + c * 8] = *(const uint4*)(Bg1 + (size_t)r * 128 + c * 8);
            }
            __syncthreads();

            float acc[2][6][4];
#pragma unroll
            for (int mi = 0; mi < 2; mi++)
#pragma unroll
                for (int ni = 0; ni < 6; ni++)
#pragma unroll
                    for (int c = 0; c < 4; c++) acc[mi][ni][c] = 0.0f;

#pragma unroll
            for (int ks = 0; ks < 8; ks++) {
                int k0 = ks * 16;
                uint32_t a[2][4];
#pragma unroll
                for (int mi = 0; mi < 2; mi++) {
                    int r = m0 + mi * 16 + gid;
                    a[mi][0] = *(const uint32_t*)&A_s[r * LDS_PAD + k0 + tid4 * 2];
                    a[mi][1] = *(const uint32_t*)&A_s[(r + 8) * LDS_PAD + k0 + tid4 * 2];
                    a[mi][2] = *(const uint32_t*)&A_s[r * LDS_PAD + k0 + 8 + tid4 * 2];
                    a[mi][3] = *(const uint32_t*)&A_s[(r + 8) * LDS_PAD + k0 + 8 + tid4 * 2];
                }
#pragma unroll
                for (int bp = 0; bp < 2; bp++) {
                    const __half* Bp = B_s[bp];
#pragma unroll
                    for (int ni = 0; ni < 6; ni++) {
                        int nr = n0 + ni * 8 + gid;
                        uint32_t b0 = *(const uint32_t*)&Bp[nr * LDS_PAD + k0 + tid4 * 2];
                        uint32_t b1v = *(const uint32_t*)&Bp[nr * LDS_PAD + k0 + 8 + tid4 * 2];
                        mma_f16(acc[0][ni], a[0], b0, b1v);
                        mma_f16(acc[1][ni], a[1], b0, b1v);
                    }
                }
            }

#pragma unroll
            for (int mi = 0; mi < 2; mi++) {
#pragma unroll
                for (int half = 0; half < 2; half++) {
                    int row = m0 + mi * 16 + gid + half * 8;
                    int node = row0 + row;
#pragma unroll
                    for (int ni = 0; ni < 6; ni++) {
                        int col = nh * 96 + n0 + ni * 8 + tid4 * 2;
                        int t = col >> 6, cin = col & 63;
                        *(__half2*)(z + (size_t)t * NPAD * 64 + (size_t)node * 64 + cin) =
                            __floats2half2_rn(acc[mi][ni][half * 2], acc[mi][ni][half * 2 + 1]);
                    }
                }
            }
        }
    }
}

// ---------------------------------------------------------------------------
// layer-2 aggregation (proven form, unchanged)
// ---------------------------------------------------------------------------
__device__ __forceinline__ void fma_h2(float2& acc, uint32_t zv, float c) {
    float2 f = __half22float2(*reinterpret_cast<__half2*>(&zv));
    acc.x += f.x * c; acc.y += f.y * c;
}

__global__ void __launch_bounds__(256)
k_agg2(const __half* __restrict__ z, const float* __restrict__ dinv,
       const int* __restrict__ off, const int2* __restrict__ csr,
       const float* __restrict__ b2, float* __restrict__ out, int n) {
    int wid = threadIdx.x >> 5, lane = threadIdx.x & 31;
    int node = blockIdx.x * 8 + wid;
    if (node >= n) return;
    int f0 = lane * 2;
    float2 acc = make_float2(
        __ldg(&b2[f0]) + __ldg(&b2[64 + f0]) + __ldg(&b2[128 + f0]),
        __ldg(&b2[f0 + 1]) + __ldg(&b2[64 + f0 + 1]) + __ldg(&b2[128 + f0 + 1]));
#pragma unroll
    for (int t = 0; t < 3; t++) {
        const uint32_t* zt = (const uint32_t*)(z + (size_t)t * NPAD * F2);
        int idx = t * n + node;
        int row_s = __ldg(&off[idx]);
        int row_e = (idx == 3 * n - 1) ? 3 * EMAX : __ldg(&off[idx + 1]);
        float di = __ldg(&dinv[idx]);
        fma_h2(acc, __ldg(zt + (size_t)node * 32 + lane), di * di);
        int e = row_s;
        for (; e + 4 <= row_e; e += 4) {
            int2 p0 = __ldg(&csr[e]);
            int2 p1 = __ldg(&csr[e + 1]);
            int2 p2 = __ldg(&csr[e + 2]);
            int2 p3 = __ldg(&csr[e + 3]);
            uint32_t v0 = __ldg(zt + (size_t)p0.x * 32 + lane);
            uint32_t v1 = __ldg(zt + (size_t)p1.x * 32 + lane);
            uint32_t v2 = __ldg(zt + (size_t)p2.x * 32 + lane);
            uint32_t v3 = __ldg(zt + (size_t)p3.x * 32 + lane);
            fma_h2(acc, v0, __int_as_float(p0.y));
            fma_h2(acc, v1, __int_as_float(p1.y));
            fma_h2(acc, v2, __int_as_float(p2.y));
            fma_h2(acc, v3, __int_as_float(p3.y));
        }
        for (; e < row_e; e++) {
            int2 p = __ldg(&csr[e]);
            fma_h2(acc, __ldg(zt + (size_t)p.x * 32 + lane), __int_as_float(p.y));
        }
    }
    acc.x *= (1.0f / 3.0f); acc.y *= (1.0f / 3.0f);
    ((float2*)out)[(size_t)node * 32 + lane] = acc;
}

// ---------------------------------------------------------------------------
// launch
// ---------------------------------------------------------------------------
static inline int cdiv(long a, long b) { return (int)((a + b - 1) / b); }

extern "C" void kernel_launch(void* const* d_in, const int* in_sizes, int n_in,
                              void* d_out, int out_size) {
    const float* x    = (const float*)d_in[0];
    const int*   edges= (const int*)  d_in[1];
    const float* W1   = (const float*)d_in[2];
    const float* b1   = (const float*)d_in[3];
    const float* W2   = (const float*)d_in[4];
    const float* b2   = (const float*)d_in[5];
    float* out = (float*)d_out;

    const int n = in_sizes[0] / F1;
    const int E = in_sizes[1] / 6;

    cudaFuncSetAttribute(k_gemm_fused, cudaFuncAttributeMaxDynamicSharedMemorySize, GF_SMEM);

    int *hist, *chunk, *off, *cursor, *partial;
    float *dinv;
    int2* csr;
    __half *xh, *y, *z, *w1t0, *w1t1, *w2t0, *w2t1;
    cudaGetSymbolAddress((void**)&hist,    g_hist);
    cudaGetSymbolAddress((void**)&chunk,   g_chunk);
    cudaGetSymbolAddress((void**)&off,     g_off);
    cudaGetSymbolAddress((void**)&cursor,  g_cursor);
    cudaGetSymbolAddress((void**)&partial, g_partial);
    cudaGetSymbolAddress((void**)&dinv,    g_dinv);
    cudaGetSymbolAddress((void**)&csr,     g_csr);
    cudaGetSymbolAddress((void**)&xh,      g_xh);
    cudaGetSymbolAddress((void**)&y,       g_y);
    cudaGetSymbolAddress((void**)&z,       g_z);
    cudaGetSymbolAddress((void**)&w1t0,    g_w1t0);
    cudaGetSymbolAddress((void**)&w1t1,    g_w1t1);
    cudaGetSymbolAddress((void**)&w2t0,    g_w2t0);
    cudaGetSymbolAddress((void**)&w2t1,    g_w2t1);

    const int TB = 256;
    const int tot = 3 * n;
    const int vblocks = cdiv(tot, 1024);
    const int gblocks = NPAD / 128;
    const int nwb = cdiv(n, 8);
    const long e3q = 3L * (E >> 2);
    const long prep_total = (long)n * 32 + 3L * 128 * 128 + 3L * 128 * 64 + tot;

    // fused prep (x->fp16, weight splits, hist zero)
    k_prep<<<cdiv(prep_total, TB), TB>>>(x, xh, W1, w1t0, w1t1, W2, w2t0, w2t1, hist, n);

    // CSR build
    k_hist4   <<<cdiv(e3q, TB), TB>>>(edges, hist, E, n);
    k_scan1v  <<<vblocks, 256>>>(hist, chunk, partial, tot);
    k_scan2   <<<1, 1024>>>(partial, vblocks);
    k_scan3fv <<<vblocks, 256>>>(chunk, partial, hist, off, cursor, dinv, tot);
    k_permute4<<<cdiv(e3q, TB), TB>>>(edges, dinv, cursor, csr, E, n);

    // layer 1 aggregation (one warp per (relation, node))
    {
        dim3 grid(nwb, 3);
        k_agg1<<<grid, 256>>>(xh, dinv, off, csr, y, n);
    }

    // fused GEMM (layer-1 transform + relu + layer-2 transform, h in smem only)
    k_gemm_fused<<<gblocks, 256, GF_SMEM>>>(y, w1t0, w1t1, b1, w2t0, w2t1, z);

    // layer 2 aggregation
    k_agg2<<<nwb, 256>>>(z, dinv, off, csr, b2, out, n);
}

// round 17
// speedup vs baseline: 1.0107x; 1.0059x over previous
#include <cuda_runtime.h>
#include <cuda_bf16.h>
#include <cuda_fp16.h>
#include <cstdint>

static constexpr int F1 = 128;
static constexpr int F2 = 64;
static constexpr int NMAX = 100000;
static constexpr int NPAD = 100096;       // 782 * 128
static constexpr int EMAX = 1600000;
static constexpr int TOT  = 3 * NMAX;

// ---------------------------------------------------------------------------
// device scratch (zero-initialized at module load; padded rows stay 0 forever)
// ---------------------------------------------------------------------------
__device__ int   g_hist   [TOT];
__device__ int   g_chunk  [TOT];
__device__ int   g_off    [TOT];
__device__ int   g_cursor [TOT];
__device__ int   g_partial[2048];
__device__ float g_dinv   [TOT];
__device__ int2  g_csr    [3 * EMAX];
__device__ __half g_xh  [(size_t)NPAD * F1];       // fp16 x
__device__ __half g_y   [(size_t)3 * NPAD * F1];   // fp16 y
__device__ __half g_z   [(size_t)3 * NPAD * F2];   // fp16 z
__device__ __half g_w1t0[3 * 128 * 128];           // fp16 W1^T hi
__device__ __half g_w1t1[3 * 128 * 128];           // fp16 W1^T lo
__device__ __half g_w2t0[3 * 64 * 128];            // fp16 W2^T hi, stacked [192][128]
__device__ __half g_w2t1[3 * 64 * 128];

// ---------------------------------------------------------------------------
// mma.sync f16
// ---------------------------------------------------------------------------
__device__ __forceinline__ void mma_f16(float* c, const uint32_t* a, uint32_t b0, uint32_t b1) {
    asm volatile("mma.sync.aligned.m16n8k16.row.col.f32.f16.f16.f32 "
        "{%0,%1,%2,%3}, {%4,%5,%6,%7}, {%8,%9}, {%0,%1,%2,%3};"
        : "+f"(c[0]), "+f"(c[1]), "+f"(c[2]), "+f"(c[3])
        : "r"(a[0]), "r"(a[1]), "r"(a[2]), "r"(a[3]), "r"(b0), "r"(b1));
}

// ---------------------------------------------------------------------------
// fused prep: x->fp16 ; W1/W2 fp16 splits ; zero hist
// ---------------------------------------------------------------------------
__device__ __forceinline__ void wsplit_one(const float* __restrict__ W, __half* __restrict__ o0,
                                           __half* __restrict__ o1, int j, int K, int N) {
    int k = j % K;
    int nn = (j / K) % N;
    int t = j / (K * N);
    float w = __ldg(&W[((size_t)t * K + k) * N + nn]);
    __half h0 = __float2half_rn(w);
    float r = w - __half2float(h0);
    size_t o = ((size_t)t * N + nn) * K + k;
    o0[o] = h0;
    o1[o] = __float2half_rn(r);
}

__global__ void k_prep(const float* __restrict__ x, __half* __restrict__ xh,
                       const float* __restrict__ W1, __half* __restrict__ w1t0,
                       __half* __restrict__ w1t1,
                       const float* __restrict__ W2, __half* __restrict__ w2t0,
                       __half* __restrict__ w2t1, int* __restrict__ hist, int n) {
    int i = blockIdx.x * blockDim.x + threadIdx.x;
    int nx = n * 32;
    const int w1n = 3 * 128 * 128, w2n = 3 * 128 * 64;
    if (i < nx) {
        float4 v = __ldg((const float4*)x + i);
        __half2* o = (__half2*)xh + (size_t)i * 2;
        o[0] = __floats2half2_rn(v.x, v.y);
        o[1] = __floats2half2_rn(v.z, v.w);
    } else if (i < nx + w1n) {
        wsplit_one(W1, w1t0, w1t1, i - nx, 128, 128);
    } else if (i < nx + w1n + w2n) {
        wsplit_one(W2, w2t0, w2t1, i - nx - w1n, 128, 64);
    } else if (i < nx + w1n + w2n + 3 * n) {
        hist[i - nx - w1n - w2n] = 0;
    }
}

// ---------------------------------------------------------------------------
// CSR build
// ---------------------------------------------------------------------------
__global__ void k_hist4(const int* __restrict__ edges, int* __restrict__ hist, int E, int n) {
    int i = blockIdx.x * blockDim.x + threadIdx.x;
    int eq = E >> 2;
    if (i >= 3 * eq) return;
    int t = i / eq, g = i - t * eq;
    int4 d = __ldg((const int4*)(edges + (size_t)t * 2 * E + E) + g);
    int* h = hist + t * n;
    atomicAdd(&h[d.x], 1);
    atomicAdd(&h[d.y], 1);
    atomicAdd(&h[d.z], 1);
    atomicAdd(&h[d.w], 1);
}

template<int NW>
__device__ __forceinline__ int block_excl_scan(int v, int tid, int* total) {
    __shared__ int wsum[NW];
    int lane = tid & 31, w = tid >> 5;
    int inc = v;
#pragma unroll
    for (int o = 1; o < 32; o <<= 1) {
        int t = __shfl_up_sync(0xffffffffu, inc, o);
        if (lane >= o) inc += t;
    }
    if (lane == 31) wsum[w] = inc;
    __syncthreads();
    if (w == 0) {
        int s = (lane < NW) ? wsum[lane] : 0;
#pragma unroll
        for (int o = 1; o < NW; o <<= 1) {
            int t = __shfl_up_sync(0xffffffffu, s, o);
            if (lane >= o) s += t;
        }
        if (lane < NW) wsum[lane] = s;
    }
    __syncthreads();
    int wbase = (w == 0) ? 0 : wsum[w - 1];
    *total = wsum[NW - 1];
    __syncthreads();
    return wbase + inc - v;
}

// scan1: 4 elements per thread (1024 per block)
__global__ void k_scan1v(const int* __restrict__ in, int* __restrict__ chunk,
                         int* __restrict__ partial, int total) {
    int tid = threadIdx.x;
    int base = blockIdx.x * 1024 + tid * 4;
    int v0 = 0, v1 = 0, v2 = 0, v3 = 0;
    if (base + 3 < total) {
        int4 v = *(const int4*)(in + base);
        v0 = v.x; v1 = v.y; v2 = v.z; v3 = v.w;
    } else if (base < total) {
        v0 = in[base];
        if (base + 1 < total) v1 = in[base + 1];
        if (base + 2 < total) v2 = in[base + 2];
    }
    int tsum;
    int ex = block_excl_scan<8>(v0 + v1 + v2 + v3, tid, &tsum);
    if (base + 3 < total) {
        int4 o = make_int4(ex, ex + v0, ex + v0 + v1, ex + v0 + v1 + v2);
        *(int4*)(chunk + base) = o;
    } else if (base < total) {
        chunk[base] = ex;
        if (base + 1 < total) chunk[base + 1] = ex + v0;
        if (base + 2 < total) chunk[base + 2] = ex + v0 + v1;
    }
    if (tid == 0) partial[blockIdx.x] = tsum;
}
__global__ void k_scan2(int* __restrict__ partial, int nblocks) {
    __shared__ int running;
    int tid = threadIdx.x;
    if (tid == 0) running = 0;
    __syncthreads();
    for (int base = 0; base < nblocks; base += 1024) {
        int i = base + tid;
        int v = (i < nblocks) ? partial[i] : 0;
        int tsum;
        int ex = block_excl_scan<32>(v, tid, &tsum);
        if (i < nblocks) partial[i] = ex + running;
        __syncthreads();
        if (tid == 0) running += tsum;
        __syncthreads();
    }
}
// scan3: 4 elements per thread; fused off/cursor/dinv
__global__ void k_scan3fv(const int* __restrict__ chunk, const int* __restrict__ partial,
                          const int* __restrict__ hist, int* __restrict__ off,
                          int* __restrict__ cursor, float* __restrict__ dinv, int total) {
    int base = blockIdx.x * 1024 + threadIdx.x * 4;
    int pb = partial[blockIdx.x];
    if (base + 3 < total) {
        int4 c = *(const int4*)(chunk + base);
        int4 h = *(const int4*)(hist + base);
        int4 o = make_int4(c.x + pb, c.y + pb, c.z + pb, c.w + pb);
        *(int4*)(off + base) = o;
        *(int4*)(cursor + base) = o;
        float4 d = make_float4(rsqrtf((float)h.x + 1.0f), rsqrtf((float)h.y + 1.0f),
                               rsqrtf((float)h.z + 1.0f), rsqrtf((float)h.w + 1.0f));
        *(float4*)(dinv + base) = d;
    } else {
        for (int j = 0; j < 4; j++) {
            int i = base + j;
            if (i < total) {
                int v = chunk[i] + pb;
                off[i] = v;
                cursor[i] = v;
                dinv[i] = rsqrtf((float)hist[i] + 1.0f);
            }
        }
    }
}
__global__ void k_permute4(const int* __restrict__ edges, const float* __restrict__ dinv,
                           int* __restrict__ cursor, int2* __restrict__ csr, int E, int n) {
    int i = blockIdx.x * blockDim.x + threadIdx.x;
    int eq = E >> 2;
    if (i >= 3 * eq) return;
    int t = i / eq, g = i - t * eq;
    const int* base = edges + (size_t)t * 2 * E;
    int4 s4 = __ldg((const int4*)base + g);
    int4 d4 = __ldg((const int4*)(base + E) + g);
    const float* dv = dinv + t * n;
    int* cur = cursor + t * n;
#pragma unroll
    for (int j = 0; j < 4; j++) {
        int s = (j == 0) ? s4.x : (j == 1) ? s4.y : (j == 2) ? s4.z : s4.w;
        int d = (j == 0) ? d4.x : (j == 1) ? d4.y : (j == 2) ? d4.z : d4.w;
        int pos = atomicAdd(&cur[d], 1);
        float c = __ldg(&dv[s]) * __ldg(&dv[d]);
        csr[pos] = make_int2(s, __float_as_int(c));
    }
}

// ---------------------------------------------------------------------------
// layer-1 aggregation (winner form): one warp per (relation,node)
// ---------------------------------------------------------------------------
__device__ __forceinline__ void fma_h4(float4& acc, uint2 xv, float c) {
    float2 f0 = __half22float2(*reinterpret_cast<__half2*>(&xv.x));
    float2 f1 = __half22float2(*reinterpret_cast<__half2*>(&xv.y));
    acc.x += f0.x * c; acc.y += f0.y * c; acc.z += f1.x * c; acc.w += f1.y * c;
}

__global__ void __launch_bounds__(256)
k_agg1(const __half* __restrict__ xh, const float* __restrict__ dinv,
       const int* __restrict__ off, const int2* __restrict__ csr,
       __half* __restrict__ y, int n) {
    int wid = threadIdx.x >> 5, lane = threadIdx.x & 31;
    int node = blockIdx.x * 8 + wid;
    if (node >= n) return;
    int t = blockIdx.y;
    int idx = t * n + node;
    int row_s = __ldg(&off[idx]);
    int row_e = (idx == 3 * n - 1) ? 3 * EMAX : __ldg(&off[idx + 1]);
    float di = __ldg(&dinv[idx]);
    const uint2* xv = (const uint2*)xh;
    float4 acc = make_float4(0.f, 0.f, 0.f, 0.f);
    fma_h4(acc, __ldg(xv + (size_t)node * 32 + lane), di * di);
    int e = row_s;
    for (; e + 4 <= row_e; e += 4) {
        int2 p0 = __ldg(&csr[e]);
        int2 p1 = __ldg(&csr[e + 1]);
        int2 p2 = __ldg(&csr[e + 2]);
        int2 p3 = __ldg(&csr[e + 3]);
        uint2 v0 = __ldg(xv + (size_t)p0.x * 32 + lane);
        uint2 v1 = __ldg(xv + (size_t)p1.x * 32 + lane);
        uint2 v2 = __ldg(xv + (size_t)p2.x * 32 + lane);
        uint2 v3 = __ldg(xv + (size_t)p3.x * 32 + lane);
        fma_h4(acc, v0, __int_as_float(p0.y));
        fma_h4(acc, v1, __int_as_float(p1.y));
        fma_h4(acc, v2, __int_as_float(p2.y));
        fma_h4(acc, v3, __int_as_float(p3.y));
    }
    for (; e < row_e; e++) {
        int2 p = __ldg(&csr[e]);
        fma_h4(acc, __ldg(xv + (size_t)p.x * 32 + lane), __int_as_float(p.y));
    }
    size_t base = ((size_t)t * NPAD + node) * 64 + lane * 2;
    ((__half2*)y)[base]     = __floats2half2_rn(acc.x, acc.y);
    ((__half2*)y)[base + 1] = __floats2half2_rn(acc.z, acc.w);
}

// ---------------------------------------------------------------------------
// FUSED GEMM v2 (winner, exact): 104960 B smem
// ---------------------------------------------------------------------------
static constexpr int LDS_PAD = 136;
static constexpr int GF_SMEM = 104448 + 512;
__global__ void __launch_bounds__(256)
k_gemm_fused(const __half* __restrict__ y, const __half* __restrict__ w10,
             const __half* __restrict__ w11, const float* __restrict__ b1,
             const __half* __restrict__ w20, const __half* __restrict__ w21,
             __half* __restrict__ z) {
    extern __shared__ char smem[];
    __half* A_s = (__half*)smem;
    float* sumb = (float*)(smem + 104448);

    const int tid = threadIdx.x, wid = tid >> 5, lane = tid & 31;
    const int gid = lane >> 2, tid4 = lane & 3;
    const int row0 = blockIdx.x * 128;
    const int m0 = (wid & 3) * 32;

    if (tid < 128) sumb[tid] = __ldg(&b1[tid]) + __ldg(&b1[128 + tid]) + __ldg(&b1[256 + tid]);

    // ---------------- phase 1: h tile into A_s ----------------
    {
        __half* B_s[2] = { (__half*)(smem + 34816), (__half*)(smem + 69632) };
        const int n0 = (wid >> 2) * 64;

        float acc[2][8][4];
#pragma unroll
        for (int mi = 0; mi < 2; mi++)
#pragma unroll
            for (int ni = 0; ni < 8; ni++)
#pragma unroll
                for (int c = 0; c < 4; c++) acc[mi][ni][c] = 0.0f;

        for (int t = 0; t < 3; t++) {
            const __half* Ag  = y   + ((size_t)t * NPAD + row0) * 128;
            const __half* Bg0 = w10 + (size_t)t * 16384;
            const __half* Bg1 = w11 + (size_t)t * 16384;
            __syncthreads();
#pragma unroll
            for (int i = tid; i < 2048; i += 256) {
                int r = i >> 4, c = i & 15;
                *(uint4*)&A_s[r * LDS_PAD + c * 8]    = *(const uint4*)(Ag  + (size_t)r * 128 + c * 8);
                *(uint4*)&B_s[0][r * LDS_PAD + c * 8] = *(const uint4*)(Bg0 + (size_t)r * 128 + c * 8);
                *(uint4*)&B_s[1][r * LDS_PAD + c * 8] = *(const uint4*)(Bg1 + (size_t)r * 128 + c * 8);
            }
            __syncthreads();
#pragma unroll
            for (int ks = 0; ks < 8; ks++) {
                int k0 = ks * 16;
                uint32_t a[2][4];
#pragma unroll
                for (int mi = 0; mi < 2; mi++) {
                    int r = m0 + mi * 16 + gid;
                    a[mi][0] = *(const uint32_t*)&A_s[r * LDS_PAD + k0 + tid4 * 2];
                    a[mi][1] = *(const uint32_t*)&A_s[(r + 8) * LDS_PAD + k0 + tid4 * 2];
                    a[mi][2] = *(const uint32_t*)&A_s[r * LDS_PAD + k0 + 8 + tid4 * 2];
                    a[mi][3] = *(const uint32_t*)&A_s[(r + 8) * LDS_PAD + k0 + 8 + tid4 * 2];
                }
#pragma unroll
                for (int bp = 0; bp < 2; bp++) {
                    const __half* Bp = B_s[bp];
#pragma unroll
                    for (int ni = 0; ni < 8; ni++) {
                        int nr = n0 + ni * 8 + gid;
                        uint32_t b0 = *(const uint32_t*)&Bp[nr * LDS_PAD + k0 + tid4 * 2];
                        uint32_t b1v = *(const uint32_t*)&Bp[nr * LDS_PAD + k0 + 8 + tid4 * 2];
                        mma_f16(acc[0][ni], a[0], b0, b1v);
                        mma_f16(acc[1][ni], a[1], b0, b1v);
                    }
                }
            }
        }
        __syncthreads();   // all A_s/B_s reads of phase 1 done; write h tile
#pragma unroll
        for (int mi = 0; mi < 2; mi++) {
#pragma unroll
            for (int half = 0; half < 2; half++) {
                int row = m0 + mi * 16 + gid + half * 8;
#pragma unroll
                for (int ni = 0; ni < 8; ni++) {
                    int col = n0 + ni * 8 + tid4 * 2;
                    float f0 = fmaxf((acc[mi][ni][half * 2]     + sumb[col])     * (1.0f / 3.0f), 0.0f);
                    float f1 = fmaxf((acc[mi][ni][half * 2 + 1] + sumb[col + 1]) * (1.0f / 3.0f), 0.0f);
                    *(__half2*)&A_s[row * LDS_PAD + col] = __floats2half2_rn(f0, f1);
                }
            }
        }
    }

    // ---------------- phase 2: z = h @ W2^T in two N-halves ----------------
    {
        __half* B_s[2] = { (__half*)(smem + 34816), (__half*)(smem + 60928) };
        const int n0 = (wid >> 2) * 48;

        for (int nh = 0; nh < 2; nh++) {
            const __half* Bg0 = w20 + (size_t)nh * 96 * 128;
            const __half* Bg1 = w21 + (size_t)nh * 96 * 128;
            __syncthreads();
#pragma unroll
            for (int i = tid; i < 1536; i += 256) {
                int r = i >> 4, c = i & 15;
                *(uint4*)&B_s[0][r * LDS_PAD + c * 8] = *(const uint4*)(Bg0 + (size_t)r * 128 + c * 8);
                *(uint4*)&B_s[1][r * LDS_PAD + c * 8] = *(const uint4*)(Bg1 + (size_t)r * 128 + c * 8);
            }
            __syncthreads();

            float acc[2][6][4];
#pragma unroll
            for (int mi = 0; mi < 2; mi++)
#pragma unroll
                for (int ni = 0; ni < 6; ni++)
#pragma unroll
                    for (int c = 0; c < 4; c++) acc[mi][ni][c] = 0.0f;

#pragma unroll
            for (int ks = 0; ks < 8; ks++) {
                int k0 = ks * 16;
                uint32_t a[2][4];
#pragma unroll
                for (int mi = 0; mi < 2; mi++) {
                    int r = m0 + mi * 16 + gid;
                    a[mi][0] = *(const uint32_t*)&A_s[r * LDS_PAD + k0 + tid4 * 2];
                    a[mi][1] = *(const uint32_t*)&A_s[(r + 8) * LDS_PAD + k0 + tid4 * 2];
                    a[mi][2] = *(const uint32_t*)&A_s[r * LDS_PAD + k0 + 8 + tid4 * 2];
                    a[mi][3] = *(const uint32_t*)&A_s[(r + 8) * LDS_PAD + k0 + 8 + tid4 * 2];
                }
#pragma unroll
                for (int bp = 0; bp < 2; bp++) {
                    const __half* Bp = B_s[bp];
#pragma unroll
                    for (int ni = 0; ni < 6; ni++) {
                        int nr = n0 + ni * 8 + gid;
                        uint32_t b0 = *(const uint32_t*)&Bp[nr * LDS_PAD + k0 + tid4 * 2];
                        uint32_t b1v = *(const uint32_t*)&Bp[nr * LDS_PAD + k0 + 8 + tid4 * 2];
                        mma_f16(acc[0][ni], a[0], b0, b1v);
                        mma_f16(acc[1][ni], a[1], b0, b1v);
                    }
                }
            }

#pragma unroll
            for (int mi = 0; mi < 2; mi++) {
#pragma unroll
                for (int half = 0; half < 2; half++) {
                    int row = m0 + mi * 16 + gid + half * 8;
                    int node = row0 + row;
#pragma unroll
                    for (int ni = 0; ni < 6; ni++) {
                        int col = nh * 96 + n0 + ni * 8 + tid4 * 2;
                        int t = col >> 6, cin = col & 63;
                        *(__half2*)(z + (size_t)t * NPAD * 64 + (size_t)node * 64 + cin) =
                            __floats2half2_rn(acc[mi][ni][half * 2], acc[mi][ni][half * 2 + 1]);
                    }
                }
            }
        }
    }
}

// ---------------------------------------------------------------------------
// layer-2 aggregation (proven form, unchanged)
// ---------------------------------------------------------------------------
__device__ __forceinline__ void fma_h2(float2& acc, uint32_t zv, float c) {
    float2 f = __half22float2(*reinterpret_cast<__half2*>(&zv));
    acc.x += f.x * c; acc.y += f.y * c;
}

__global__ void __launch_bounds__(256)
k_agg2(const __half* __restrict__ z, const float* __restrict__ dinv,
       const int* __restrict__ off, const int2* __restrict__ csr,
       const float* __restrict__ b2, float* __restrict__ out, int n) {
    int wid = threadIdx.x >> 5, lane = threadIdx.x & 31;
    int node = blockIdx.x * 8 + wid;
    if (node >= n) return;
    int f0 = lane * 2;
    float2 acc = make_float2(
        __ldg(&b2[f0]) + __ldg(&b2[64 + f0]) + __ldg(&b2[128 + f0]),
        __ldg(&b2[f0 + 1]) + __ldg(&b2[64 + f0 + 1]) + __ldg(&b2[128 + f0 + 1]));
#pragma unroll
    for (int t = 0; t < 3; t++) {
        const uint32_t* zt = (const uint32_t*)(z + (size_t)t * NPAD * F2);
        int idx = t * n + node;
        int row_s = __ldg(&off[idx]);
        int row_e = (idx == 3 * n - 1) ? 3 * EMAX : __ldg(&off[idx + 1]);
        float di = __ldg(&dinv[idx]);
        fma_h2(acc, __ldg(zt + (size_t)node * 32 + lane), di * di);
        int e = row_s;
        for (; e + 4 <= row_e; e += 4) {
            int2 p0 = __ldg(&csr[e]);
            int2 p1 = __ldg(&csr[e + 1]);
            int2 p2 = __ldg(&csr[e + 2]);
            int2 p3 = __ldg(&csr[e + 3]);
            uint32_t v0 = __ldg(zt + (size_t)p0.x * 32 + lane);
            uint32_t v1 = __ldg(zt + (size_t)p1.x * 32 + lane);
            uint32_t v2 = __ldg(zt + (size_t)p2.x * 32 + lane);
            uint32_t v3 = __ldg(zt + (size_t)p3.x * 32 + lane);
            fma_h2(acc, v0, __int_as_float(p0.y));
            fma_h2(acc, v1, __int_as_float(p1.y));
            fma_h2(acc, v2, __int_as_float(p2.y));
            fma_h2(acc, v3, __int_as_float(p3.y));
        }
        for (; e < row_e; e++) {
            int2 p = __ldg(&csr[e]);
            fma_h2(acc, __ldg(zt + (size_t)p.x * 32 + lane), __int_as_float(p.y));
        }
    }
    acc.x *= (1.0f / 3.0f); acc.y *= (1.0f / 3.0f);
    ((float2*)out)[(size_t)node * 32 + lane] = acc;
}

// ---------------------------------------------------------------------------
// launch
// ---------------------------------------------------------------------------
static inline int cdiv(long a, long b) { return (int)((a + b - 1) / b); }

extern "C" void kernel_launch(void* const* d_in, const int* in_sizes, int n_in,
                              void* d_out, int out_size) {
    const float* x    = (const float*)d_in[0];
    const int*   edges= (const int*)  d_in[1];
    const float* W1   = (const float*)d_in[2];
    const float* b1   = (const float*)d_in[3];
    const float* W2   = (const float*)d_in[4];
    const float* b2   = (const float*)d_in[5];
    float* out = (float*)d_out;

    const int n = in_sizes[0] / F1;
    const int E = in_sizes[1] / 6;

    cudaFuncSetAttribute(k_gemm_fused, cudaFuncAttributeMaxDynamicSharedMemorySize, GF_SMEM);

    int *hist, *chunk, *off, *cursor, *partial;
    float *dinv;
    int2* csr;
    __half *xh, *y, *z, *w1t0, *w1t1, *w2t0, *w2t1;
    cudaGetSymbolAddress((void**)&hist,    g_hist);
    cudaGetSymbolAddress((void**)&chunk,   g_chunk);
    cudaGetSymbolAddress((void**)&off,     g_off);
    cudaGetSymbolAddress((void**)&cursor,  g_cursor);
    cudaGetSymbolAddress((void**)&partial, g_partial);
    cudaGetSymbolAddress((void**)&dinv,    g_dinv);
    cudaGetSymbolAddress((void**)&csr,     g_csr);
    cudaGetSymbolAddress((void**)&xh,      g_xh);
    cudaGetSymbolAddress((void**)&y,       g_y);
    cudaGetSymbolAddress((void**)&z,       g_z);
    cudaGetSymbolAddress((void**)&w1t0,    g_w1t0);
    cudaGetSymbolAddress((void**)&w1t1,    g_w1t1);
    cudaGetSymbolAddress((void**)&w2t0,    g_w2t0);
    cudaGetSymbolAddress((void**)&w2t1,    g_w2t1);

    const int TB = 256;
    const int tot = 3 * n;
    const int vblocks = cdiv(tot, 1024);
    const int gblocks = NPAD / 128;
    const int nwb = cdiv(n, 8);
    const long e3q = 3L * (E >> 2);
    const long prep_total = (long)n * 32 + 3L * 128 * 128 + 3L * 128 * 64 + tot;

    // fused prep (x->fp16, weight splits, hist zero)
    k_prep<<<cdiv(prep_total, TB), TB>>>(x, xh, W1, w1t0, w1t1, W2, w2t0, w2t1, hist, n);

    // CSR build
    k_hist4   <<<cdiv(e3q, TB), TB>>>(edges, hist, E, n);
    k_scan1v  <<<vblocks, 256>>>(hist, chunk, partial, tot);
    k_scan2   <<<1, 1024>>>(partial, vblocks);
    k_scan3fv <<<vblocks, 256>>>(chunk, partial, hist, off, cursor, dinv, tot);
    k_permute4<<<cdiv(e3q, TB), TB>>>(edges, dinv, cursor, csr, E, n);

    // layer 1 aggregation (one warp per (relation, node))
    {
        dim3 grid(nwb, 3);
        k_agg1<<<grid, 256>>>(xh, dinv, off, csr, y, n);
    }

    // fused GEMM (layer-1 transform + relu + layer-2 transform, h in smem only)
    k_gemm_fused<<<gblocks, 256, GF_SMEM>>>(y, w1t0, w1t1, b1, w2t0, w2t1, z);

    // layer 2 aggregation
    k_agg2<<<nwb, 256>>>(z, dinv, off, csr, b2, out, n);
}